// round 1
// baseline (speedup 1.0000x reference)
#include <cuda_runtime.h>
#include <cuda_bf16.h>
#include <math.h>

// Problem constants
#define Bb   2
#define Ss   2048
#define HID  2048
#define NHh  16
#define QLORA 1536
#define KVLORA 512
#define NOPE 128
#define ROPED 64
#define VDIM 128
#define QKD  192
#define ROWS (Bb*Ss)          // 4096

// ---------------- scratch (device globals; no allocations allowed) ----------
__device__ float g_qc   [(size_t)ROWS * QLORA];        // 4096x1536
__device__ float g_q    [(size_t)ROWS * NHh * QKD];    // 4096x3072
__device__ float g_kvt  [(size_t)ROWS * (KVLORA+ROPED)];// 4096x576
__device__ float g_kvc  [(size_t)ROWS * KVLORA];       // 4096x512
__device__ float g_krope[(size_t)ROWS * ROPED];        // 4096x64
__device__ float g_kv   [(size_t)ROWS * NHh * (NOPE+VDIM)]; // 4096x4096
__device__ float g_attn [(size_t)ROWS * NHh * VDIM];   // 4096x2048

// ---------------- generic SGEMM: C[M,N] = A[M,K] @ B[K,N], row-major --------
// 128x128 tile, BK=8, 256 threads, 8x8 per thread.
__global__ void sgemm128(const float* __restrict__ A, const float* __restrict__ B,
                         float* __restrict__ C, int M, int N, int K) {
    __shared__ float As[8][128];
    __shared__ float Bs[8][132];

    int tid  = threadIdx.x;
    int row0 = blockIdx.y * 128;
    int col0 = blockIdx.x * 128;

    float acc[8][8];
#pragma unroll
    for (int i = 0; i < 8; i++)
#pragma unroll
        for (int j = 0; j < 8; j++) acc[i][j] = 0.f;

    int tyA = tid >> 1, txA = tid & 1;     // A: row tyA (0..127), col txA*4
    int tyB = tid >> 5, txB = tid & 31;    // B: row tyB (0..7), col txB*4

    int ry = (tid >> 4) * 8;               // local out row base
    int rx = (tid & 15) * 8;               // local out col base

    for (int k0 = 0; k0 < K; k0 += 8) {
        // load A tile (transposed into As[k][m])
        {
            int ar = row0 + tyA;
            float4 a4 = make_float4(0.f, 0.f, 0.f, 0.f);
            if (ar < M) a4 = *(const float4*)(A + (size_t)ar * K + k0 + txA * 4);
            As[txA*4+0][tyA] = a4.x;
            As[txA*4+1][tyA] = a4.y;
            As[txA*4+2][tyA] = a4.z;
            As[txA*4+3][tyA] = a4.w;
        }
        // load B tile
        {
            int bc = col0 + txB * 4;
            float4 b4 = make_float4(0.f, 0.f, 0.f, 0.f);
            if (bc < N) b4 = *(const float4*)(B + (size_t)(k0 + tyB) * N + bc);
            *(float4*)&Bs[tyB][txB * 4] = b4;
        }
        __syncthreads();

#pragma unroll
        for (int k = 0; k < 8; k++) {
            float4 a0 = *(const float4*)&As[k][ry];
            float4 a1 = *(const float4*)&As[k][ry + 4];
            float4 b0 = *(const float4*)&Bs[k][rx];
            float4 b1 = *(const float4*)&Bs[k][rx + 4];
            float a[8] = {a0.x,a0.y,a0.z,a0.w,a1.x,a1.y,a1.z,a1.w};
            float b[8] = {b0.x,b0.y,b0.z,b0.w,b1.x,b1.y,b1.z,b1.w};
#pragma unroll
            for (int i = 0; i < 8; i++)
#pragma unroll
                for (int j = 0; j < 8; j++) acc[i][j] += a[i] * b[j];
        }
        __syncthreads();
    }

    int crow = row0 + ry;
    int ccol = col0 + rx;
    if (ccol < N) {   // N is a multiple of 8 for every call here
#pragma unroll
        for (int i = 0; i < 8; i++) {
            if (crow + i < M) {
                float* cp = C + (size_t)(crow + i) * N + ccol;
                *(float4*)cp       = make_float4(acc[i][0], acc[i][1], acc[i][2], acc[i][3]);
                *(float4*)(cp + 4) = make_float4(acc[i][4], acc[i][5], acc[i][6], acc[i][7]);
            }
        }
    }
}

// ---------------- rmsnorm in place over rows of length L --------------------
__global__ void rmsnorm_rows(float* __restrict__ x, const float* __restrict__ w, int L) {
    __shared__ float red[256];
    int tid = threadIdx.x;
    float* r = x + (size_t)blockIdx.x * L;
    float ss = 0.f;
    for (int i = tid; i < L; i += 256) { float v = r[i]; ss += v * v; }
    red[tid] = ss; __syncthreads();
    for (int s = 128; s > 0; s >>= 1) {
        if (tid < s) red[tid] += red[tid + s];
        __syncthreads();
    }
    float scale = rsqrtf(red[0] / (float)L + 1e-6f);
    for (int i = tid; i < L; i += 256) r[i] = r[i] * scale * w[i];
}

// ---------------- kv split: rmsnorm first 512 -> kvc ; rope last 64 -> krope -
__global__ void kv_split(const float* __restrict__ kvt, const float* __restrict__ w,
                         const int* __restrict__ pos,
                         float* __restrict__ kvc, float* __restrict__ krope) {
    __shared__ float red[256];
    int tid = threadIdx.x;
    int row = blockIdx.x;
    const float* r = kvt + (size_t)row * (KVLORA + ROPED);
    float ss = 0.f;
    for (int i = tid; i < KVLORA; i += 256) { float v = r[i]; ss += v * v; }
    red[tid] = ss; __syncthreads();
    for (int s = 128; s > 0; s >>= 1) {
        if (tid < s) red[tid] += red[tid + s];
        __syncthreads();
    }
    float scale = rsqrtf(red[0] / (float)KVLORA + 1e-6f);
    for (int i = tid; i < KVLORA; i += 256)
        kvc[(size_t)row * KVLORA + i] = r[i] * scale * w[i];

    if (tid < 32) {
        float p = (float)pos[row];
        float inv_freq = powf(10000.f, -(float)tid / 32.f);
        float ang = p * inv_freq;
        float c = cosf(ang), s = sinf(ang);
        float x1 = r[KVLORA + tid];
        float x2 = r[KVLORA + 32 + tid];
        krope[(size_t)row * ROPED + tid]      = x1 * c - x2 * s;
        krope[(size_t)row * ROPED + 32 + tid] = x2 * c + x1 * s;
    }
}

// ---------------- rope on q (per head, last 64 of each 192) -----------------
__global__ void rope_q(float* __restrict__ q, const int* __restrict__ pos) {
    int row = blockIdx.x;
    int h = threadIdx.x >> 5;
    int i = threadIdx.x & 31;
    float* base = q + (size_t)row * (NHh * QKD) + h * QKD + NOPE;
    float p = (float)pos[row];
    float inv_freq = powf(10000.f, -(float)i / 32.f);
    float ang = p * inv_freq;
    float c = cosf(ang), s = sinf(ang);
    float x1 = base[i];
    float x2 = base[i + 32];
    base[i]      = x1 * c - x2 * s;
    base[i + 32] = x2 * c + x1 * s;
}

// ---------------- flash attention -------------------------------------------
// grid (S/64, NH, B), 256 threads. q=ty+16i, k=tx+16j strided mapping.
#define QP 196
#define KP 196
#define VP 132
#define PP 65
#define FLASH_SMEM ((64*QP + 64*KP + 64*VP + 64*PP) * 4)

__global__ void flash_kernel(const float* __restrict__ q, const float* __restrict__ kv,
                             const float* __restrict__ krope, float* __restrict__ out) {
    extern __shared__ float sm[];
    float* Qs = sm;                 // 64 x QP
    float* Ks = Qs + 64 * QP;       // 64 x KP
    float* Vs = Ks + 64 * KP;       // 64 x VP
    float* Ps = Vs + 64 * VP;       // 64 x PP

    int qt = blockIdx.x, h = blockIdx.y, b = blockIdx.z;
    int q0 = qt * 64;
    int tid = threadIdx.x;
    int ty = tid >> 4, tx = tid & 15;
    const float scale = 0.07216878364870322f; // 192^-0.5

    // load Q tile: 64 rows x 192 cols
    {
        const float* qb = q + ((size_t)(b * Ss + q0) * NHh + h) * QKD;
#pragma unroll
        for (int it = 0; it < 12; it++) {
            int e = it * 256 + tid;
            int r = e / 48, c4 = e % 48;
            float4 v4 = *(const float4*)(qb + (size_t)r * (NHh * QKD) + c4 * 4);
            *(float4*)&Qs[r * QP + c4 * 4] = v4;
        }
    }
    __syncthreads();

    float m_[4], l_[4], O[4][8];
#pragma unroll
    for (int i = 0; i < 4; i++) {
        m_[i] = -INFINITY; l_[i] = 0.f;
#pragma unroll
        for (int j = 0; j < 8; j++) O[i][j] = 0.f;
    }

    for (int kt = 0; kt <= qt; kt++) {
        // load K tile (nope 128 + rope 64) and V tile
        {
            const float* kb = kv + ((size_t)(b * Ss + kt * 64) * NHh + h) * (NOPE + VDIM);
#pragma unroll
            for (int it = 0; it < 8; it++) {
                int e = it * 256 + tid;
                int r = e >> 5, c4 = e & 31;
                float4 v4 = *(const float4*)(kb + (size_t)r * (NHh * (NOPE + VDIM)) + c4 * 4);
                *(float4*)&Ks[r * KP + c4 * 4] = v4;
            }
            const float* rb = krope + (size_t)(b * Ss + kt * 64) * ROPED;
#pragma unroll
            for (int it = 0; it < 4; it++) {
                int e = it * 256 + tid;
                int r = e >> 4, c4 = e & 15;
                float4 v4 = *(const float4*)(rb + (size_t)r * ROPED + c4 * 4);
                *(float4*)&Ks[r * KP + NOPE + c4 * 4] = v4;
            }
            const float* vb = kb + NOPE;
#pragma unroll
            for (int it = 0; it < 8; it++) {
                int e = it * 256 + tid;
                int r = e >> 5, c4 = e & 31;
                float4 v4 = *(const float4*)(vb + (size_t)r * (NHh * (NOPE + VDIM)) + c4 * 4);
                *(float4*)&Vs[r * VP + c4 * 4] = v4;
            }
        }
        __syncthreads();

        // scores 4x4 micro-tile: q = ty + 16i, k = tx + 16j
        float s4[4][4];
#pragma unroll
        for (int i = 0; i < 4; i++)
#pragma unroll
            for (int j = 0; j < 4; j++) s4[i][j] = 0.f;

#pragma unroll 4
        for (int d4 = 0; d4 < 48; d4++) {
            float4 qv[4], kvv[4];
#pragma unroll
            for (int i = 0; i < 4; i++) qv[i]  = *(const float4*)&Qs[(ty + 16 * i) * QP + d4 * 4];
#pragma unroll
            for (int j = 0; j < 4; j++) kvv[j] = *(const float4*)&Ks[(tx + 16 * j) * KP + d4 * 4];
#pragma unroll
            for (int i = 0; i < 4; i++)
#pragma unroll
                for (int j = 0; j < 4; j++) {
                    s4[i][j] += qv[i].x * kvv[j].x + qv[i].y * kvv[j].y
                              + qv[i].z * kvv[j].z + qv[i].w * kvv[j].w;
                }
        }

        // mask + online softmax
#pragma unroll
        for (int i = 0; i < 4; i++) {
            int qg = q0 + ty + 16 * i;
#pragma unroll
            for (int j = 0; j < 4; j++) {
                int kg = kt * 64 + tx + 16 * j;
                float sv = s4[i][j] * scale;
                if (kg > qg) sv = -INFINITY;
                s4[i][j] = sv;
            }
            float rm = fmaxf(fmaxf(s4[i][0], s4[i][1]), fmaxf(s4[i][2], s4[i][3]));
#pragma unroll
            for (int off = 1; off < 16; off <<= 1)
                rm = fmaxf(rm, __shfl_xor_sync(0xffffffffu, rm, off));
            float nm = fmaxf(m_[i], rm);
            float p0 = __expf(s4[i][0] - nm);
            float p1 = __expf(s4[i][1] - nm);
            float p2 = __expf(s4[i][2] - nm);
            float p3 = __expf(s4[i][3] - nm);
            float rs = p0 + p1 + p2 + p3;
#pragma unroll
            for (int off = 1; off < 16; off <<= 1)
                rs += __shfl_xor_sync(0xffffffffu, rs, off);
            float alpha = __expf(m_[i] - nm);
            l_[i] = l_[i] * alpha + rs;
            m_[i] = nm;
#pragma unroll
            for (int j = 0; j < 8; j++) O[i][j] *= alpha;
            int qrow = ty + 16 * i;
            Ps[qrow * PP + tx]      = p0;
            Ps[qrow * PP + tx + 16] = p1;
            Ps[qrow * PP + tx + 32] = p2;
            Ps[qrow * PP + tx + 48] = p3;
        }
        __syncthreads();

        // O += P @ V   (thread owns dims d = tx*8 .. tx*8+7)
#pragma unroll 8
        for (int k = 0; k < 64; k++) {
            float4 v0 = *(const float4*)&Vs[k * VP + tx * 8];
            float4 v1 = *(const float4*)&Vs[k * VP + tx * 8 + 4];
#pragma unroll
            for (int i = 0; i < 4; i++) {
                float p = Ps[(ty + 16 * i) * PP + k];
                O[i][0] += p * v0.x; O[i][1] += p * v0.y;
                O[i][2] += p * v0.z; O[i][3] += p * v0.w;
                O[i][4] += p * v1.x; O[i][5] += p * v1.y;
                O[i][6] += p * v1.z; O[i][7] += p * v1.w;
            }
        }
        __syncthreads();
    }

    // epilogue: normalize and store to [b,s, h*128 + d]
#pragma unroll
    for (int i = 0; i < 4; i++) {
        int qg = q0 + ty + 16 * i;
        float inv = 1.f / l_[i];
        float* ob = out + ((size_t)(b * Ss + qg)) * (NHh * VDIM) + h * VDIM + tx * 8;
        *(float4*)ob       = make_float4(O[i][0]*inv, O[i][1]*inv, O[i][2]*inv, O[i][3]*inv);
        *(float4*)(ob + 4) = make_float4(O[i][4]*inv, O[i][5]*inv, O[i][6]*inv, O[i][7]*inv);
    }
}

// ---------------- launch -----------------------------------------------------
extern "C" void kernel_launch(void* const* d_in, const int* in_sizes, int n_in,
                              void* d_out, int out_size) {
    const float* hs     = (const float*)d_in[0];
    const int*   pos    = (const int*)  d_in[1];
    // d_in[2] = attention_mask (pure causal; implemented analytically)
    const float* w_q_a  = (const float*)d_in[3];
    const float* q_ln   = (const float*)d_in[4];
    const float* w_q_b  = (const float*)d_in[5];
    const float* w_kv_a = (const float*)d_in[6];
    const float* kv_ln  = (const float*)d_in[7];
    const float* w_kv_b = (const float*)d_in[8];
    const float* w_o    = (const float*)d_in[9];
    float* out = (float*)d_out;

    float *qc, *q, *kvt, *kvc, *krope, *kvp, *attn;
    cudaGetSymbolAddress((void**)&qc,    g_qc);
    cudaGetSymbolAddress((void**)&q,     g_q);
    cudaGetSymbolAddress((void**)&kvt,   g_kvt);
    cudaGetSymbolAddress((void**)&kvc,   g_kvc);
    cudaGetSymbolAddress((void**)&krope, g_krope);
    cudaGetSymbolAddress((void**)&kvp,   g_kv);
    cudaGetSymbolAddress((void**)&attn,  g_attn);

    // 1) q_c = H @ w_q_a ; rmsnorm
    sgemm128<<<dim3(QLORA/128, ROWS/128), 256>>>(hs, w_q_a, qc, ROWS, QLORA, HID);
    rmsnorm_rows<<<ROWS, 256>>>(qc, q_ln, QLORA);
    // 2) q = q_c @ w_q_b
    sgemm128<<<dim3((NHh*QKD)/128, ROWS/128), 256>>>(qc, w_q_b, q, ROWS, NHh*QKD, QLORA);
    // 3) kv_comb = H @ w_kv_a
    sgemm128<<<dim3((KVLORA+ROPED+127)/128, ROWS/128), 256>>>(hs, w_kv_a, kvt, ROWS, KVLORA+ROPED, HID);
    // 4) split + rmsnorm + k-rope
    kv_split<<<ROWS, 256>>>(kvt, kv_ln, pos, kvc, krope);
    // 5) q rope (in place)
    rope_q<<<ROWS, 512>>>(q, pos);
    // 6) kv = kv_c @ w_kv_b
    sgemm128<<<dim3((NHh*(NOPE+VDIM))/128, ROWS/128), 256>>>(kvc, w_kv_b, kvp, ROWS, NHh*(NOPE+VDIM), KVLORA);
    // 7) attention
    cudaFuncSetAttribute(flash_kernel, cudaFuncAttributeMaxDynamicSharedMemorySize, FLASH_SMEM);
    flash_kernel<<<dim3(Ss/64, NHh, Bb), 256, FLASH_SMEM>>>(q, kvp, krope, attn);
    // 8) out = attn @ w_o
    sgemm128<<<dim3(HID/128, ROWS/128), 256>>>(attn, w_o, out, ROWS, HID, HID);
}

// round 3
// speedup vs baseline: 1.7033x; 1.7033x over previous
#include <cuda_runtime.h>
#include <cuda_bf16.h>
#include <math.h>
#include <cstdint>

// ---------------- problem constants ----------------
#define Bb   2
#define Ss   2048
#define HID  2048
#define NHh  16
#define QLORA 1536
#define KVLORA 512
#define NOPE 128
#define ROPED 64
#define VDIM 128
#define QKD  192
#define ROWS (Bb*Ss)          // 4096
#define WKVA_NPAD 640         // 576 padded to multiple of 128

// ---------------- fp32 scratch ----------------
__device__ float g_qc   [(size_t)ROWS * QLORA];
__device__ float g_q    [(size_t)ROWS * NHh * QKD];
__device__ float g_kvt  [(size_t)ROWS * (KVLORA+ROPED)];
__device__ float g_kvc  [(size_t)ROWS * KVLORA];
__device__ float g_krope[(size_t)ROWS * ROPED];
__device__ float g_kv   [(size_t)ROWS * NHh * (NOPE+VDIM)];
__device__ float g_attn [(size_t)ROWS * NHh * VDIM];

// ---------------- bf16 split scratch (activations) ----------------
__device__ __nv_bfloat16 g_hs_h [(size_t)ROWS*HID],    g_hs_l [(size_t)ROWS*HID];
__device__ __nv_bfloat16 g_qc_h [(size_t)ROWS*QLORA],  g_qc_l [(size_t)ROWS*QLORA];
__device__ __nv_bfloat16 g_kvc_h[(size_t)ROWS*KVLORA], g_kvc_l[(size_t)ROWS*KVLORA];
__device__ __nv_bfloat16 g_at_h [(size_t)ROWS*NHh*VDIM], g_at_l[(size_t)ROWS*NHh*VDIM];

// ---------------- bf16 split scratch (transposed weights, [N,K]) ----------
__device__ __nv_bfloat16 g_wqa_h [(size_t)QLORA*HID],            g_wqa_l [(size_t)QLORA*HID];
__device__ __nv_bfloat16 g_wqb_h [(size_t)(NHh*QKD)*QLORA],      g_wqb_l [(size_t)(NHh*QKD)*QLORA];
__device__ __nv_bfloat16 g_wkva_h[(size_t)WKVA_NPAD*HID],        g_wkva_l[(size_t)WKVA_NPAD*HID];
__device__ __nv_bfloat16 g_wkvb_h[(size_t)(NHh*(NOPE+VDIM))*KVLORA], g_wkvb_l[(size_t)(NHh*(NOPE+VDIM))*KVLORA];
__device__ __nv_bfloat16 g_wo_h  [(size_t)HID*(NHh*VDIM)],       g_wo_l  [(size_t)HID*(NHh*VDIM)];

// ================= helpers =================
__device__ __forceinline__ uint32_t smem_u32(const void* p) {
    uint32_t a;
    asm("{ .reg .u64 t; cvta.to.shared.u64 t, %1; cvt.u32.u64 %0, t; }" : "=r"(a) : "l"(p));
    return a;
}

#define LDSM4(r, a) asm volatile( \
    "ldmatrix.sync.aligned.m8n8.x4.shared.b16 {%0,%1,%2,%3}, [%4];" \
    : "=r"((r)[0]),"=r"((r)[1]),"=r"((r)[2]),"=r"((r)[3]) : "r"(a))

#define MMA16816(d, a, b0v, b1v) asm volatile( \
    "mma.sync.aligned.m16n8k16.row.col.f32.bf16.bf16.f32 " \
    "{%0,%1,%2,%3},{%4,%5,%6,%7},{%8,%9},{%0,%1,%2,%3};" \
    : "+f"((d)[0]),"+f"((d)[1]),"+f"((d)[2]),"+f"((d)[3]) \
    : "r"((a)[0]),"r"((a)[1]),"r"((a)[2]),"r"((a)[3]), "r"(b0v),"r"(b1v))

#define CP_ASYNC16(sa, ga) asm volatile( \
    "cp.async.cg.shared.global [%0], [%1], 16;" :: "r"(sa), "l"(ga))
#define CP_COMMIT() asm volatile("cp.async.commit_group;" ::: "memory")
#define CP_WAIT1()  asm volatile("cp.async.wait_group 1;" ::: "memory")
#define CP_WAIT0()  asm volatile("cp.async.wait_group 0;" ::: "memory")

// ================= bf16x2 HMMA GEMM =================
// C[M,N] = A[M,K] @ Bt[N,K]^T, hi/lo split, 3 MMA passes.
// CTA 128x128, BK=32, 256 threads (4x2 warps, warp tile 32x64), double buffered.
#define BK 32
#define PITCH 40                       // bf16 per smem row (80B, conflict-free ldmatrix)
#define TILE_B (128*PITCH*2)           // 10240 B
#define STAGE_B (4*TILE_B)             // 40960 B (Ah|Al|Bh|Bl)
#define GEMM_SMEM (2*STAGE_B)          // 81920 B

__global__ void __launch_bounds__(256, 1) mma_gemm(
    const __nv_bfloat16* __restrict__ Ah, const __nv_bfloat16* __restrict__ Al,
    const __nv_bfloat16* __restrict__ Bh, const __nv_bfloat16* __restrict__ Bl,
    float* __restrict__ C, int M, int N, int K) {
    extern __shared__ char sm[];
    uint32_t sbase = smem_u32(sm);

    int tid = threadIdx.x, lane = tid & 31, wid = tid >> 5;
    int warpM = wid & 3, warpN = wid >> 2;
    int row0 = blockIdx.y * 128, col0 = blockIdx.x * 128;

    const __nv_bfloat16* gsrc[4] = {
        Ah + (size_t)row0 * K, Al + (size_t)row0 * K,
        Bh + (size_t)col0 * K, Bl + (size_t)col0 * K };

    auto issue_loads = [&](int c, int s) {
        int k0 = c * BK;
        uint32_t st = sbase + s * STAGE_B;
#pragma unroll
        for (int t = 0; t < 4; t++) {
#pragma unroll
            for (int j = 0; j < 2; j++) {
                int seg = tid + j * 256;
                int r = seg >> 2, cc = seg & 3;
                const __nv_bfloat16* g = gsrc[t] + (size_t)r * K + k0 + cc * 8;
                uint32_t sa = st + t * TILE_B + r * (PITCH * 2) + cc * 16;
                CP_ASYNC16(sa, g);
            }
        }
        CP_COMMIT();
    };

    float acc[2][8][4];
#pragma unroll
    for (int i = 0; i < 2; i++)
#pragma unroll
        for (int j = 0; j < 8; j++)
#pragma unroll
            for (int k = 0; k < 4; k++) acc[i][j][k] = 0.f;

    // precomputed ldmatrix local offsets
    int a_r = warpM * 32 + (lane & 15);
    int a_c8 = (lane >> 4) << 3;
    int b_r = warpN * 64 + ((lane >> 4) << 3) + (lane & 7);
    int b_c8 = ((lane >> 3) & 1) << 3;

    auto compute = [&](int s) {
        uint32_t st = sbase + s * STAGE_B;
#pragma unroll
        for (int ki = 0; ki < 2; ki++) {
            uint32_t ah[2][4], al[2][4];
#pragma unroll
            for (int mi = 0; mi < 2; mi++) {
                uint32_t off = (uint32_t)((a_r + mi * 16) * (PITCH * 2) + (ki * 16 + a_c8) * 2);
                LDSM4(ah[mi], st + off);
                LDSM4(al[mi], st + TILE_B + off);
            }
            uint32_t bh[4][4], bl[4][4];
#pragma unroll
            for (int nb = 0; nb < 4; nb++) {
                uint32_t off = (uint32_t)((b_r + nb * 16) * (PITCH * 2) + (ki * 16 + b_c8) * 2);
                LDSM4(bh[nb], st + 2 * TILE_B + off);
                LDSM4(bl[nb], st + 3 * TILE_B + off);
            }
#pragma unroll
            for (int mi = 0; mi < 2; mi++)
#pragma unroll
                for (int nb = 0; nb < 4; nb++) {
                    MMA16816(acc[mi][2*nb],   ah[mi], bh[nb][0], bh[nb][1]);
                    MMA16816(acc[mi][2*nb],   ah[mi], bl[nb][0], bl[nb][1]);
                    MMA16816(acc[mi][2*nb],   al[mi], bh[nb][0], bh[nb][1]);
                    MMA16816(acc[mi][2*nb+1], ah[mi], bh[nb][2], bh[nb][3]);
                    MMA16816(acc[mi][2*nb+1], ah[mi], bl[nb][2], bl[nb][3]);
                    MMA16816(acc[mi][2*nb+1], al[mi], bh[nb][2], bh[nb][3]);
                }
        }
    };

    int nc = K / BK;
    issue_loads(0, 0);
    for (int c = 0; c < nc; c++) {
        int s = c & 1;
        if (c + 1 < nc) { issue_loads(c + 1, s ^ 1); CP_WAIT1(); }
        else            { CP_WAIT0(); }
        __syncthreads();
        compute(s);
        __syncthreads();
    }

    // epilogue
    int g = lane >> 2, t = lane & 3;
#pragma unroll
    for (int mi = 0; mi < 2; mi++)
#pragma unroll
        for (int n8 = 0; n8 < 8; n8++) {
            int col = col0 + warpN * 64 + n8 * 8 + t * 2;
            if (col < N) {
                int r0 = row0 + warpM * 32 + mi * 16 + g;
                float* p0 = C + (size_t)r0 * N + col;
                p0[0] = acc[mi][n8][0]; p0[1] = acc[mi][n8][1];
                float* p1 = p0 + (size_t)8 * N;
                p1[0] = acc[mi][n8][2]; p1[1] = acc[mi][n8][3];
            }
        }
}

// ================= conversion / transpose kernels =================
__global__ void convert_split(const float* __restrict__ x, __nv_bfloat16* __restrict__ h,
                              __nv_bfloat16* __restrict__ l, size_t n) {
    size_t i = ((size_t)blockIdx.x * 256 + threadIdx.x) * 4;
    if (i >= n) return;
    float4 v = *(const float4*)(x + i);
    float a[4] = {v.x, v.y, v.z, v.w};
    __nv_bfloat16 hh[4], ll[4];
#pragma unroll
    for (int j = 0; j < 4; j++) {
        hh[j] = __float2bfloat16(a[j]);
        ll[j] = __float2bfloat16(a[j] - __bfloat162float(hh[j]));
    }
    *(__nv_bfloat162*)(h + i)     = __nv_bfloat162(hh[0], hh[1]);
    *(__nv_bfloat162*)(h + i + 2) = __nv_bfloat162(hh[2], hh[3]);
    *(__nv_bfloat162*)(l + i)     = __nv_bfloat162(ll[0], ll[1]);
    *(__nv_bfloat162*)(l + i + 2) = __nv_bfloat162(ll[2], ll[3]);
}

// W[K,N] fp32 -> T[Npad,K] bf16 hi/lo (rows >= N zero-filled)
__global__ void transpose_split(const float* __restrict__ W, __nv_bfloat16* __restrict__ Th,
                                __nv_bfloat16* __restrict__ Tl, int K, int N) {
    __shared__ float tile[32][33];
    int n0 = blockIdx.x * 32, k0 = blockIdx.y * 32;
    int tx = threadIdx.x, ty = threadIdx.y;
#pragma unroll
    for (int i = 0; i < 4; i++) {
        int k = k0 + ty + i * 8, n = n0 + tx;
        tile[ty + i * 8][tx] = (n < N) ? W[(size_t)k * N + n] : 0.f;
    }
    __syncthreads();
#pragma unroll
    for (int i = 0; i < 4; i++) {
        int n = n0 + ty + i * 8;
        float v = tile[tx][ty + i * 8];
        __nv_bfloat16 h = __float2bfloat16(v);
        __nv_bfloat16 l = __float2bfloat16(v - __bfloat162float(h));
        Th[(size_t)n * K + k0 + tx] = h;
        Tl[(size_t)n * K + k0 + tx] = l;
    }
}

// ================= rmsnorm / rope / kv-split =================
__global__ void rmsnorm_rows(float* __restrict__ x, const float* __restrict__ w, int L) {
    __shared__ float red[256];
    int tid = threadIdx.x;
    float* r = x + (size_t)blockIdx.x * L;
    float ss = 0.f;
    for (int i = tid; i < L; i += 256) { float v = r[i]; ss += v * v; }
    red[tid] = ss; __syncthreads();
    for (int s = 128; s > 0; s >>= 1) { if (tid < s) red[tid] += red[tid + s]; __syncthreads(); }
    float scale = rsqrtf(red[0] / (float)L + 1e-6f);
    for (int i = tid; i < L; i += 256) r[i] = r[i] * scale * w[i];
}

__global__ void kv_split(const float* __restrict__ kvt, const float* __restrict__ w,
                         const int* __restrict__ pos,
                         float* __restrict__ kvc, float* __restrict__ krope) {
    __shared__ float red[256];
    int tid = threadIdx.x;
    int row = blockIdx.x;
    const float* r = kvt + (size_t)row * (KVLORA + ROPED);
    float ss = 0.f;
    for (int i = tid; i < KVLORA; i += 256) { float v = r[i]; ss += v * v; }
    red[tid] = ss; __syncthreads();
    for (int s = 128; s > 0; s >>= 1) { if (tid < s) red[tid] += red[tid + s]; __syncthreads(); }
    float scale = rsqrtf(red[0] / (float)KVLORA + 1e-6f);
    for (int i = tid; i < KVLORA; i += 256)
        kvc[(size_t)row * KVLORA + i] = r[i] * scale * w[i];
    if (tid < 32) {
        float p = (float)pos[row];
        float inv_freq = powf(10000.f, -(float)tid / 32.f);
        float ang = p * inv_freq;
        float c = cosf(ang), s = sinf(ang);
        float x1 = r[KVLORA + tid];
        float x2 = r[KVLORA + 32 + tid];
        krope[(size_t)row * ROPED + tid]      = x1 * c - x2 * s;
        krope[(size_t)row * ROPED + 32 + tid] = x2 * c + x1 * s;
    }
}

__global__ void rope_q(float* __restrict__ q, const int* __restrict__ pos) {
    int row = blockIdx.x;
    int h = threadIdx.x >> 5;
    int i = threadIdx.x & 31;
    float* base = q + (size_t)row * (NHh * QKD) + h * QKD + NOPE;
    float p = (float)pos[row];
    float inv_freq = powf(10000.f, -(float)i / 32.f);
    float ang = p * inv_freq;
    float c = cosf(ang), s = sinf(ang);
    float x1 = base[i];
    float x2 = base[i + 32];
    base[i]      = x1 * c - x2 * s;
    base[i + 32] = x2 * c + x1 * s;
}

// ================= flash attention (fp32, unchanged) =================
#define QP 196
#define KP 196
#define VP 132
#define PP 65
#define FLASH_SMEM ((64*QP + 64*KP + 64*VP + 64*PP) * 4)

__global__ void flash_kernel(const float* __restrict__ q, const float* __restrict__ kv,
                             const float* __restrict__ krope, float* __restrict__ out) {
    extern __shared__ float smf[];
    float* Qs = smf;
    float* Ks = Qs + 64 * QP;
    float* Vs = Ks + 64 * KP;
    float* Ps = Vs + 64 * VP;

    int qt = blockIdx.x, h = blockIdx.y, b = blockIdx.z;
    int q0 = qt * 64;
    int tid = threadIdx.x;
    int ty = tid >> 4, tx = tid & 15;
    const float scale = 0.07216878364870322f;

    {
        const float* qb = q + ((size_t)(b * Ss + q0) * NHh + h) * QKD;
#pragma unroll
        for (int it = 0; it < 12; it++) {
            int e = it * 256 + tid;
            int r = e / 48, c4 = e % 48;
            float4 v4 = *(const float4*)(qb + (size_t)r * (NHh * QKD) + c4 * 4);
            *(float4*)&Qs[r * QP + c4 * 4] = v4;
        }
    }
    __syncthreads();

    float m_[4], l_[4], O[4][8];
#pragma unroll
    for (int i = 0; i < 4; i++) {
        m_[i] = -INFINITY; l_[i] = 0.f;
#pragma unroll
        for (int j = 0; j < 8; j++) O[i][j] = 0.f;
    }

    for (int kt = 0; kt <= qt; kt++) {
        {
            const float* kb = kv + ((size_t)(b * Ss + kt * 64) * NHh + h) * (NOPE + VDIM);
#pragma unroll
            for (int it = 0; it < 8; it++) {
                int e = it * 256 + tid;
                int r = e >> 5, c4 = e & 31;
                float4 v4 = *(const float4*)(kb + (size_t)r * (NHh * (NOPE + VDIM)) + c4 * 4);
                *(float4*)&Ks[r * KP + c4 * 4] = v4;
            }
            const float* rb = krope + (size_t)(b * Ss + kt * 64) * ROPED;
#pragma unroll
            for (int it = 0; it < 4; it++) {
                int e = it * 256 + tid;
                int r = e >> 4, c4 = e & 15;
                float4 v4 = *(const float4*)(rb + (size_t)r * ROPED + c4 * 4);
                *(float4*)&Ks[r * KP + NOPE + c4 * 4] = v4;
            }
            const float* vb = kb + NOPE;
#pragma unroll
            for (int it = 0; it < 8; it++) {
                int e = it * 256 + tid;
                int r = e >> 5, c4 = e & 31;
                float4 v4 = *(const float4*)(vb + (size_t)r * (NHh * (NOPE + VDIM)) + c4 * 4);
                *(float4*)&Vs[r * VP + c4 * 4] = v4;
            }
        }
        __syncthreads();

        float s4[4][4];
#pragma unroll
        for (int i = 0; i < 4; i++)
#pragma unroll
            for (int j = 0; j < 4; j++) s4[i][j] = 0.f;

#pragma unroll 4
        for (int d4 = 0; d4 < 48; d4++) {
            float4 qv[4], kvv[4];
#pragma unroll
            for (int i = 0; i < 4; i++) qv[i]  = *(const float4*)&Qs[(ty + 16 * i) * QP + d4 * 4];
#pragma unroll
            for (int j = 0; j < 4; j++) kvv[j] = *(const float4*)&Ks[(tx + 16 * j) * KP + d4 * 4];
#pragma unroll
            for (int i = 0; i < 4; i++)
#pragma unroll
                for (int j = 0; j < 4; j++)
                    s4[i][j] += qv[i].x * kvv[j].x + qv[i].y * kvv[j].y
                              + qv[i].z * kvv[j].z + qv[i].w * kvv[j].w;
        }

#pragma unroll
        for (int i = 0; i < 4; i++) {
            int qg = q0 + ty + 16 * i;
#pragma unroll
            for (int j = 0; j < 4; j++) {
                int kg = kt * 64 + tx + 16 * j;
                float sv = s4[i][j] * scale;
                if (kg > qg) sv = -INFINITY;
                s4[i][j] = sv;
            }
            float rm = fmaxf(fmaxf(s4[i][0], s4[i][1]), fmaxf(s4[i][2], s4[i][3]));
#pragma unroll
            for (int off = 1; off < 16; off <<= 1)
                rm = fmaxf(rm, __shfl_xor_sync(0xffffffffu, rm, off));
            float nm = fmaxf(m_[i], rm);
            float p0 = __expf(s4[i][0] - nm);
            float p1 = __expf(s4[i][1] - nm);
            float p2 = __expf(s4[i][2] - nm);
            float p3 = __expf(s4[i][3] - nm);
            float rs = p0 + p1 + p2 + p3;
#pragma unroll
            for (int off = 1; off < 16; off <<= 1)
                rs += __shfl_xor_sync(0xffffffffu, rs, off);
            float alpha = __expf(m_[i] - nm);
            l_[i] = l_[i] * alpha + rs;
            m_[i] = nm;
#pragma unroll
            for (int j = 0; j < 8; j++) O[i][j] *= alpha;
            int qrow = ty + 16 * i;
            Ps[qrow * PP + tx]      = p0;
            Ps[qrow * PP + tx + 16] = p1;
            Ps[qrow * PP + tx + 32] = p2;
            Ps[qrow * PP + tx + 48] = p3;
        }
        __syncthreads();

#pragma unroll 8
        for (int k = 0; k < 64; k++) {
            float4 v0 = *(const float4*)&Vs[k * VP + tx * 8];
            float4 v1 = *(const float4*)&Vs[k * VP + tx * 8 + 4];
#pragma unroll
            for (int i = 0; i < 4; i++) {
                float p = Ps[(ty + 16 * i) * PP + k];
                O[i][0] += p * v0.x; O[i][1] += p * v0.y;
                O[i][2] += p * v0.z; O[i][3] += p * v0.w;
                O[i][4] += p * v1.x; O[i][5] += p * v1.y;
                O[i][6] += p * v1.z; O[i][7] += p * v1.w;
            }
        }
        __syncthreads();
    }

#pragma unroll
    for (int i = 0; i < 4; i++) {
        int qg = q0 + ty + 16 * i;
        float inv = 1.f / l_[i];
        float* ob = out + ((size_t)(b * Ss + qg)) * (NHh * VDIM) + h * VDIM + tx * 8;
        *(float4*)ob       = make_float4(O[i][0]*inv, O[i][1]*inv, O[i][2]*inv, O[i][3]*inv);
        *(float4*)(ob + 4) = make_float4(O[i][4]*inv, O[i][5]*inv, O[i][6]*inv, O[i][7]*inv);
    }
}

// ================= launch =================
extern "C" void kernel_launch(void* const* d_in, const int* in_sizes, int n_in,
                              void* d_out, int out_size) {
    const float* hs     = (const float*)d_in[0];
    const int*   pos    = (const int*)  d_in[1];
    const float* w_q_a  = (const float*)d_in[3];
    const float* q_ln   = (const float*)d_in[4];
    const float* w_q_b  = (const float*)d_in[5];
    const float* w_kv_a = (const float*)d_in[6];
    const float* kv_ln  = (const float*)d_in[7];
    const float* w_kv_b = (const float*)d_in[8];
    const float* w_o    = (const float*)d_in[9];
    float* out = (float*)d_out;

    float *qc, *q, *kvt, *kvc, *krope, *kvp, *attn;
    cudaGetSymbolAddress((void**)&qc,    g_qc);
    cudaGetSymbolAddress((void**)&q,     g_q);
    cudaGetSymbolAddress((void**)&kvt,   g_kvt);
    cudaGetSymbolAddress((void**)&kvc,   g_kvc);
    cudaGetSymbolAddress((void**)&krope, g_krope);
    cudaGetSymbolAddress((void**)&kvp,   g_kv);
    cudaGetSymbolAddress((void**)&attn,  g_attn);

    __nv_bfloat16 *hs_h,*hs_l,*qc_h,*qc_l,*kvc_h,*kvc_l,*at_h,*at_l;
    __nv_bfloat16 *wqa_h,*wqa_l,*wqb_h,*wqb_l,*wkva_h,*wkva_l,*wkvb_h,*wkvb_l,*wo_h,*wo_l;
    cudaGetSymbolAddress((void**)&hs_h,  g_hs_h);  cudaGetSymbolAddress((void**)&hs_l,  g_hs_l);
    cudaGetSymbolAddress((void**)&qc_h,  g_qc_h);  cudaGetSymbolAddress((void**)&qc_l,  g_qc_l);
    cudaGetSymbolAddress((void**)&kvc_h, g_kvc_h); cudaGetSymbolAddress((void**)&kvc_l, g_kvc_l);
    cudaGetSymbolAddress((void**)&at_h,  g_at_h);  cudaGetSymbolAddress((void**)&at_l,  g_at_l);
    cudaGetSymbolAddress((void**)&wqa_h, g_wqa_h); cudaGetSymbolAddress((void**)&wqa_l, g_wqa_l);
    cudaGetSymbolAddress((void**)&wqb_h, g_wqb_h); cudaGetSymbolAddress((void**)&wqb_l, g_wqb_l);
    cudaGetSymbolAddress((void**)&wkva_h,g_wkva_h);cudaGetSymbolAddress((void**)&wkva_l,g_wkva_l);
    cudaGetSymbolAddress((void**)&wkvb_h,g_wkvb_h);cudaGetSymbolAddress((void**)&wkvb_l,g_wkvb_l);
    cudaGetSymbolAddress((void**)&wo_h,  g_wo_h);  cudaGetSymbolAddress((void**)&wo_l,  g_wo_l);

    cudaFuncSetAttribute(mma_gemm, cudaFuncAttributeMaxDynamicSharedMemorySize, GEMM_SMEM);
    cudaFuncSetAttribute(flash_kernel, cudaFuncAttributeMaxDynamicSharedMemorySize, FLASH_SMEM);

    dim3 tb(32, 8);

    // weight transposes + hs convert (independent)
    transpose_split<<<dim3(QLORA/32, HID/32), tb>>>(w_q_a, wqa_h, wqa_l, HID, QLORA);
    transpose_split<<<dim3((NHh*QKD)/32, QLORA/32), tb>>>(w_q_b, wqb_h, wqb_l, QLORA, NHh*QKD);
    transpose_split<<<dim3(WKVA_NPAD/32, HID/32), tb>>>(w_kv_a, wkva_h, wkva_l, HID, KVLORA+ROPED);
    transpose_split<<<dim3((NHh*(NOPE+VDIM))/32, KVLORA/32), tb>>>(w_kv_b, wkvb_h, wkvb_l, KVLORA, NHh*(NOPE+VDIM));
    transpose_split<<<dim3(HID/32, (NHh*VDIM)/32), tb>>>(w_o, wo_h, wo_l, NHh*VDIM, HID);
    convert_split<<<(ROWS*(size_t)HID/4 + 255)/256, 256>>>(hs, hs_h, hs_l, (size_t)ROWS*HID);

    // G1: qc = hs @ w_q_a
    mma_gemm<<<dim3(QLORA/128, ROWS/128), 256, GEMM_SMEM>>>(hs_h, hs_l, wqa_h, wqa_l, qc, ROWS, QLORA, HID);
    rmsnorm_rows<<<ROWS, 256>>>(qc, q_ln, QLORA);
    convert_split<<<(ROWS*(size_t)QLORA/4 + 255)/256, 256>>>(qc, qc_h, qc_l, (size_t)ROWS*QLORA);

    // G2: q = qc @ w_q_b
    mma_gemm<<<dim3((NHh*QKD)/128, ROWS/128), 256, GEMM_SMEM>>>(qc_h, qc_l, wqb_h, wqb_l, q, ROWS, NHh*QKD, QLORA);

    // G3: kvt = hs @ w_kv_a  (N=576, B padded to 640 rows)
    mma_gemm<<<dim3(WKVA_NPAD/128, ROWS/128), 256, GEMM_SMEM>>>(hs_h, hs_l, wkva_h, wkva_l, kvt, ROWS, KVLORA+ROPED, HID);

    kv_split<<<ROWS, 256>>>(kvt, kv_ln, pos, kvc, krope);
    convert_split<<<(ROWS*(size_t)KVLORA/4 + 255)/256, 256>>>(kvc, kvc_h, kvc_l, (size_t)ROWS*KVLORA);
    rope_q<<<ROWS, 512>>>(q, pos);

    // G4: kv = kvc @ w_kv_b
    mma_gemm<<<dim3((NHh*(NOPE+VDIM))/128, ROWS/128), 256, GEMM_SMEM>>>(kvc_h, kvc_l, wkvb_h, wkvb_l, kvp, ROWS, NHh*(NOPE+VDIM), KVLORA);

    // attention
    flash_kernel<<<dim3(Ss/64, NHh, Bb), 256, FLASH_SMEM>>>(q, kvp, krope, attn);
    convert_split<<<(ROWS*(size_t)(NHh*VDIM)/4 + 255)/256, 256>>>(attn, at_h, at_l, (size_t)ROWS*NHh*VDIM);

    // G5: out = attn @ w_o
    mma_gemm<<<dim3(HID/128, ROWS/128), 256, GEMM_SMEM>>>(at_h, at_l, wo_h, wo_l, out, ROWS, HID, HID);
}

// round 4
// speedup vs baseline: 2.6161x; 1.5359x over previous
#include <cuda_runtime.h>
#include <cuda_bf16.h>
#include <math.h>
#include <cstdint>

// ---------------- problem constants ----------------
#define Bb   2
#define Ss   2048
#define HID  2048
#define NHh  16
#define QLORA 1536
#define KVLORA 512
#define NOPE 128
#define ROPED 64
#define VDIM 128
#define QKD  192
#define ROWS (Bb*Ss)          // 4096
#define WKVA_NPAD 640
#define SCALEF 0.07216878364870322f

// ---------------- fp32 scratch ----------------
__device__ float g_qc   [(size_t)ROWS * QLORA];
__device__ float g_q    [(size_t)ROWS * NHh * QKD];
__device__ float g_kvt  [(size_t)ROWS * (KVLORA+ROPED)];
__device__ float g_kvc  [(size_t)ROWS * KVLORA];
__device__ float g_krope[(size_t)ROWS * ROPED];
__device__ float g_kv   [(size_t)ROWS * NHh * (NOPE+VDIM)];
__device__ float g_attn [(size_t)ROWS * NHh * VDIM];

// ---------------- bf16 split scratch (activations) ----------------
__device__ __nv_bfloat16 g_hs_h [(size_t)ROWS*HID],    g_hs_l [(size_t)ROWS*HID];
__device__ __nv_bfloat16 g_qc_h [(size_t)ROWS*QLORA],  g_qc_l [(size_t)ROWS*QLORA];
__device__ __nv_bfloat16 g_kvc_h[(size_t)ROWS*KVLORA], g_kvc_l[(size_t)ROWS*KVLORA];
__device__ __nv_bfloat16 g_at_h [(size_t)ROWS*NHh*VDIM], g_at_l[(size_t)ROWS*NHh*VDIM];

// ---------------- bf16 split scratch (transposed weights, [N,K]) ----------
__device__ __nv_bfloat16 g_wqa_h [(size_t)QLORA*HID],            g_wqa_l [(size_t)QLORA*HID];
__device__ __nv_bfloat16 g_wqb_h [(size_t)(NHh*QKD)*QLORA],      g_wqb_l [(size_t)(NHh*QKD)*QLORA];
__device__ __nv_bfloat16 g_wkva_h[(size_t)WKVA_NPAD*HID],        g_wkva_l[(size_t)WKVA_NPAD*HID];
__device__ __nv_bfloat16 g_wkvb_h[(size_t)(NHh*(NOPE+VDIM))*KVLORA], g_wkvb_l[(size_t)(NHh*(NOPE+VDIM))*KVLORA];
__device__ __nv_bfloat16 g_wo_h  [(size_t)HID*(NHh*VDIM)],       g_wo_l  [(size_t)HID*(NHh*VDIM)];

// ---------------- flash bf16 buffers, [b,h,s,d] contiguous ----------
__device__ __nv_bfloat16 g_qfh[(size_t)ROWS*NHh*QKD], g_qfl[(size_t)ROWS*NHh*QKD];
__device__ __nv_bfloat16 g_kfh[(size_t)ROWS*NHh*QKD], g_kfl[(size_t)ROWS*NHh*QKD];
__device__ __nv_bfloat16 g_vfh[(size_t)ROWS*NHh*VDIM], g_vfl[(size_t)ROWS*NHh*VDIM];

// ================= helpers =================
__device__ __forceinline__ uint32_t smem_u32(const void* p) {
    uint32_t a;
    asm("{ .reg .u64 t; cvta.to.shared.u64 t, %1; cvt.u32.u64 %0, t; }" : "=r"(a) : "l"(p));
    return a;
}

#define LDSM4(r, a) asm volatile( \
    "ldmatrix.sync.aligned.m8n8.x4.shared.b16 {%0,%1,%2,%3}, [%4];" \
    : "=r"((r)[0]),"=r"((r)[1]),"=r"((r)[2]),"=r"((r)[3]) : "r"(a))

#define LDSM4T(r, a) asm volatile( \
    "ldmatrix.sync.aligned.m8n8.x4.trans.shared.b16 {%0,%1,%2,%3}, [%4];" \
    : "=r"((r)[0]),"=r"((r)[1]),"=r"((r)[2]),"=r"((r)[3]) : "r"(a))

#define MMA16816(d, a, b0v, b1v) asm volatile( \
    "mma.sync.aligned.m16n8k16.row.col.f32.bf16.bf16.f32 " \
    "{%0,%1,%2,%3},{%4,%5,%6,%7},{%8,%9},{%0,%1,%2,%3};" \
    : "+f"((d)[0]),"+f"((d)[1]),"+f"((d)[2]),"+f"((d)[3]) \
    : "r"((a)[0]),"r"((a)[1]),"r"((a)[2]),"r"((a)[3]), "r"(b0v),"r"(b1v))

#define CP_ASYNC16(sa, ga) asm volatile( \
    "cp.async.cg.shared.global [%0], [%1], 16;" :: "r"(sa), "l"(ga))
#define CP_COMMIT() asm volatile("cp.async.commit_group;" ::: "memory")
#define CP_WAIT1()  asm volatile("cp.async.wait_group 1;" ::: "memory")
#define CP_WAIT0()  asm volatile("cp.async.wait_group 0;" ::: "memory")

// ================= bf16x2 HMMA GEMM (unchanged from R3) =================
#define BK 32
#define PITCH 40
#define TILE_B (128*PITCH*2)
#define STAGE_B (4*TILE_B)
#define GEMM_SMEM (2*STAGE_B)

__global__ void __launch_bounds__(256, 1) mma_gemm(
    const __nv_bfloat16* __restrict__ Ah, const __nv_bfloat16* __restrict__ Al,
    const __nv_bfloat16* __restrict__ Bh, const __nv_bfloat16* __restrict__ Bl,
    float* __restrict__ C, int M, int N, int K) {
    extern __shared__ char sm[];
    uint32_t sbase = smem_u32(sm);

    int tid = threadIdx.x, lane = tid & 31, wid = tid >> 5;
    int warpM = wid & 3, warpN = wid >> 2;
    int row0 = blockIdx.y * 128, col0 = blockIdx.x * 128;

    const __nv_bfloat16* gsrc[4] = {
        Ah + (size_t)row0 * K, Al + (size_t)row0 * K,
        Bh + (size_t)col0 * K, Bl + (size_t)col0 * K };

    auto issue_loads = [&](int c, int s) {
        int k0 = c * BK;
        uint32_t st = sbase + s * STAGE_B;
#pragma unroll
        for (int t = 0; t < 4; t++) {
#pragma unroll
            for (int j = 0; j < 2; j++) {
                int seg = tid + j * 256;
                int r = seg >> 2, cc = seg & 3;
                const __nv_bfloat16* g = gsrc[t] + (size_t)r * K + k0 + cc * 8;
                uint32_t sa = st + t * TILE_B + r * (PITCH * 2) + cc * 16;
                CP_ASYNC16(sa, g);
            }
        }
        CP_COMMIT();
    };

    float acc[2][8][4];
#pragma unroll
    for (int i = 0; i < 2; i++)
#pragma unroll
        for (int j = 0; j < 8; j++)
#pragma unroll
            for (int k = 0; k < 4; k++) acc[i][j][k] = 0.f;

    int a_r = warpM * 32 + (lane & 15);
    int a_c8 = (lane >> 4) << 3;
    int b_r = warpN * 64 + ((lane >> 4) << 3) + (lane & 7);
    int b_c8 = ((lane >> 3) & 1) << 3;

    auto compute = [&](int s) {
        uint32_t st = sbase + s * STAGE_B;
#pragma unroll
        for (int ki = 0; ki < 2; ki++) {
            uint32_t ah[2][4], al[2][4];
#pragma unroll
            for (int mi = 0; mi < 2; mi++) {
                uint32_t off = (uint32_t)((a_r + mi * 16) * (PITCH * 2) + (ki * 16 + a_c8) * 2);
                LDSM4(ah[mi], st + off);
                LDSM4(al[mi], st + TILE_B + off);
            }
            uint32_t bh[4][4], bl[4][4];
#pragma unroll
            for (int nb = 0; nb < 4; nb++) {
                uint32_t off = (uint32_t)((b_r + nb * 16) * (PITCH * 2) + (ki * 16 + b_c8) * 2);
                LDSM4(bh[nb], st + 2 * TILE_B + off);
                LDSM4(bl[nb], st + 3 * TILE_B + off);
            }
#pragma unroll
            for (int mi = 0; mi < 2; mi++)
#pragma unroll
                for (int nb = 0; nb < 4; nb++) {
                    MMA16816(acc[mi][2*nb],   ah[mi], bh[nb][0], bh[nb][1]);
                    MMA16816(acc[mi][2*nb],   ah[mi], bl[nb][0], bl[nb][1]);
                    MMA16816(acc[mi][2*nb],   al[mi], bh[nb][0], bh[nb][1]);
                    MMA16816(acc[mi][2*nb+1], ah[mi], bh[nb][2], bh[nb][3]);
                    MMA16816(acc[mi][2*nb+1], ah[mi], bl[nb][2], bl[nb][3]);
                    MMA16816(acc[mi][2*nb+1], al[mi], bh[nb][2], bh[nb][3]);
                }
        }
    };

    int nc = K / BK;
    issue_loads(0, 0);
    for (int c = 0; c < nc; c++) {
        int s = c & 1;
        if (c + 1 < nc) { issue_loads(c + 1, s ^ 1); CP_WAIT1(); }
        else            { CP_WAIT0(); }
        __syncthreads();
        compute(s);
        __syncthreads();
    }

    int g = lane >> 2, t = lane & 3;
#pragma unroll
    for (int mi = 0; mi < 2; mi++)
#pragma unroll
        for (int n8 = 0; n8 < 8; n8++) {
            int col = col0 + warpN * 64 + n8 * 8 + t * 2;
            if (col < N) {
                int r0 = row0 + warpM * 32 + mi * 16 + g;
                float* p0 = C + (size_t)r0 * N + col;
                p0[0] = acc[mi][n8][0]; p0[1] = acc[mi][n8][1];
                float* p1 = p0 + (size_t)8 * N;
                p1[0] = acc[mi][n8][2]; p1[1] = acc[mi][n8][3];
            }
        }
}

// ================= conversion / transpose kernels =================
__global__ void convert_split(const float* __restrict__ x, __nv_bfloat16* __restrict__ h,
                              __nv_bfloat16* __restrict__ l, size_t n) {
    size_t i = ((size_t)blockIdx.x * 256 + threadIdx.x) * 4;
    if (i >= n) return;
    float4 v = *(const float4*)(x + i);
    float a[4] = {v.x, v.y, v.z, v.w};
    __nv_bfloat16 hh[4], ll[4];
#pragma unroll
    for (int j = 0; j < 4; j++) {
        hh[j] = __float2bfloat16(a[j]);
        ll[j] = __float2bfloat16(a[j] - __bfloat162float(hh[j]));
    }
    *(__nv_bfloat162*)(h + i)     = __nv_bfloat162(hh[0], hh[1]);
    *(__nv_bfloat162*)(h + i + 2) = __nv_bfloat162(hh[2], hh[3]);
    *(__nv_bfloat162*)(l + i)     = __nv_bfloat162(ll[0], ll[1]);
    *(__nv_bfloat162*)(l + i + 2) = __nv_bfloat162(ll[2], ll[3]);
}

__global__ void transpose_split(const float* __restrict__ W, __nv_bfloat16* __restrict__ Th,
                                __nv_bfloat16* __restrict__ Tl, int K, int N) {
    __shared__ float tile[32][33];
    int n0 = blockIdx.x * 32, k0 = blockIdx.y * 32;
    int tx = threadIdx.x, ty = threadIdx.y;
#pragma unroll
    for (int i = 0; i < 4; i++) {
        int k = k0 + ty + i * 8, n = n0 + tx;
        tile[ty + i * 8][tx] = (n < N) ? W[(size_t)k * N + n] : 0.f;
    }
    __syncthreads();
#pragma unroll
    for (int i = 0; i < 4; i++) {
        int n = n0 + ty + i * 8;
        float v = tile[tx][ty + i * 8];
        __nv_bfloat16 h = __float2bfloat16(v);
        __nv_bfloat16 l = __float2bfloat16(v - __bfloat162float(h));
        Th[(size_t)n * K + k0 + tx] = h;
        Tl[(size_t)n * K + k0 + tx] = l;
    }
}

// ================= rmsnorm / rope / kv-split =================
__global__ void rmsnorm_rows(float* __restrict__ x, const float* __restrict__ w, int L) {
    __shared__ float red[256];
    int tid = threadIdx.x;
    float* r = x + (size_t)blockIdx.x * L;
    float ss = 0.f;
    for (int i = tid; i < L; i += 256) { float v = r[i]; ss += v * v; }
    red[tid] = ss; __syncthreads();
    for (int s = 128; s > 0; s >>= 1) { if (tid < s) red[tid] += red[tid + s]; __syncthreads(); }
    float scale = rsqrtf(red[0] / (float)L + 1e-6f);
    for (int i = tid; i < L; i += 256) r[i] = r[i] * scale * w[i];
}

__global__ void kv_split(const float* __restrict__ kvt, const float* __restrict__ w,
                         const int* __restrict__ pos,
                         float* __restrict__ kvc, float* __restrict__ krope) {
    __shared__ float red[256];
    int tid = threadIdx.x;
    int row = blockIdx.x;
    const float* r = kvt + (size_t)row * (KVLORA + ROPED);
    float ss = 0.f;
    for (int i = tid; i < KVLORA; i += 256) { float v = r[i]; ss += v * v; }
    red[tid] = ss; __syncthreads();
    for (int s = 128; s > 0; s >>= 1) { if (tid < s) red[tid] += red[tid + s]; __syncthreads(); }
    float scale = rsqrtf(red[0] / (float)KVLORA + 1e-6f);
    for (int i = tid; i < KVLORA; i += 256)
        kvc[(size_t)row * KVLORA + i] = r[i] * scale * w[i];
    if (tid < 32) {
        float p = (float)pos[row];
        float inv_freq = powf(10000.f, -(float)tid / 32.f);
        float ang = p * inv_freq;
        float c = cosf(ang), s = sinf(ang);
        float x1 = r[KVLORA + tid];
        float x2 = r[KVLORA + 32 + tid];
        krope[(size_t)row * ROPED + tid]      = x1 * c - x2 * s;
        krope[(size_t)row * ROPED + 32 + tid] = x2 * c + x1 * s;
    }
}

__global__ void rope_q(float* __restrict__ q, const int* __restrict__ pos) {
    int row = blockIdx.x;
    int h = threadIdx.x >> 5;
    int i = threadIdx.x & 31;
    float* base = q + (size_t)row * (NHh * QKD) + h * QKD + NOPE;
    float p = (float)pos[row];
    float inv_freq = powf(10000.f, -(float)i / 32.f);
    float ang = p * inv_freq;
    float c = cosf(ang), s = sinf(ang);
    float x1 = base[i];
    float x2 = base[i + 32];
    base[i]      = x1 * c - x2 * s;
    base[i + 32] = x2 * c + x1 * s;
}

// ================= flash prep: build [b,h,s,d] bf16 hi/lo =================
__global__ void prep_q(const float* __restrict__ q, __nv_bfloat16* __restrict__ qh,
                       __nv_bfloat16* __restrict__ ql) {
    int row = blockIdx.x;                  // b*Ss + s
    int b = row >> 11, s = row & 2047;
    for (int e = threadIdx.x; e < NHh * QKD; e += 256) {
        int h = e / QKD, d = e % QKD;
        float v = q[(size_t)row * (NHh * QKD) + e] * SCALEF;
        __nv_bfloat16 hi = __float2bfloat16(v);
        size_t o = ((size_t)(b * NHh + h) * Ss + s) * QKD + d;
        qh[o] = hi;
        ql[o] = __float2bfloat16(v - __bfloat162float(hi));
    }
}

__global__ void prep_kv(const float* __restrict__ kv, const float* __restrict__ krope,
                        __nv_bfloat16* __restrict__ kh, __nv_bfloat16* __restrict__ kl,
                        __nv_bfloat16* __restrict__ vh, __nv_bfloat16* __restrict__ vl) {
    int row = blockIdx.x;
    int b = row >> 11, s = row & 2047;
    for (int e = threadIdx.x; e < NHh * QKD; e += 256) {
        int h = e / QKD, d = e % QKD;
        float v = (d < NOPE) ? kv[(size_t)row * (NHh * 256) + h * 256 + d]
                             : krope[(size_t)row * ROPED + d - NOPE];
        __nv_bfloat16 hi = __float2bfloat16(v);
        size_t o = ((size_t)(b * NHh + h) * Ss + s) * QKD + d;
        kh[o] = hi;
        kl[o] = __float2bfloat16(v - __bfloat162float(hi));
    }
    for (int e = threadIdx.x; e < NHh * VDIM; e += 256) {
        int h = e >> 7, d = e & 127;
        float v = kv[(size_t)row * (NHh * 256) + h * 256 + NOPE + d];
        __nv_bfloat16 hi = __float2bfloat16(v);
        size_t o = ((size_t)(b * NHh + h) * Ss + s) * VDIM + d;
        vh[o] = hi;
        vl[o] = __float2bfloat16(v - __bfloat162float(hi));
    }
}

// ================= tensor-core flash attention =================
// CTA: 64 q rows, 128 threads (4 warps x 16 rows). Key tiles of 64, dbl-buffered.
#define KQ_PITCH 400            // bytes per K/Q smem row (200 bf16)
#define V_PITCH  272            // bytes per V smem row (136 bf16)
#define Q_HALF   (64*KQ_PITCH)  // 25600
#define K_HALF   (64*KQ_PITCH)
#define V_HALF   (64*V_PITCH)   // 17408
#define OFF_Q    0
#define OFF_K    (2*Q_HALF)             // 51200 (stage stride 2*K_HALF)
#define OFF_V    (OFF_K + 4*K_HALF)     // 153600 (stage stride 2*V_HALF)
#define FLASH_SMEM (OFF_V + 4*V_HALF)   // 223232

__global__ void __launch_bounds__(128, 1) flash_mma(
    const __nv_bfloat16* __restrict__ qh, const __nv_bfloat16* __restrict__ ql,
    const __nv_bfloat16* __restrict__ kh, const __nv_bfloat16* __restrict__ kl,
    const __nv_bfloat16* __restrict__ vh, const __nv_bfloat16* __restrict__ vl,
    float* __restrict__ out) {
    extern __shared__ char sm[];
    uint32_t sb = smem_u32(sm);

    int qt = blockIdx.x, h = blockIdx.y, b = blockIdx.z;
    int q0 = qt * 64;
    int tid = threadIdx.x, lane = tid & 31, w = tid >> 5;
    int bh = b * NHh + h;

    const __nv_bfloat16* qhb = qh + ((size_t)bh * Ss + q0) * QKD;
    const __nv_bfloat16* qlb = ql + ((size_t)bh * Ss + q0) * QKD;
    const __nv_bfloat16* khb = kh + (size_t)bh * Ss * QKD;
    const __nv_bfloat16* klb = kl + (size_t)bh * Ss * QKD;
    const __nv_bfloat16* vhb = vh + (size_t)bh * Ss * VDIM;
    const __nv_bfloat16* vlb = vl + (size_t)bh * Ss * VDIM;

    // ---- load Q (both halves) ----
#pragma unroll
    for (int i = 0; i < 12; i++) {
        int e = tid + i * 128;            // 1536 chunks per half
        int r = e / 24, c = e % 24;
        CP_ASYNC16(sb + OFF_Q + r * KQ_PITCH + c * 16, qhb + (size_t)r * QKD + c * 8);
        CP_ASYNC16(sb + OFF_Q + Q_HALF + r * KQ_PITCH + c * 16, qlb + (size_t)r * QKD + c * 8);
    }

    auto load_kv = [&](int kt, int s) {
        int k0 = kt * 64;
        uint32_t kst = sb + OFF_K + s * (2 * K_HALF);
        uint32_t vst = sb + OFF_V + s * (2 * V_HALF);
#pragma unroll
        for (int i = 0; i < 12; i++) {
            int e = tid + i * 128;
            int r = e / 24, c = e % 24;
            CP_ASYNC16(kst + r * KQ_PITCH + c * 16, khb + (size_t)(k0 + r) * QKD + c * 8);
            CP_ASYNC16(kst + K_HALF + r * KQ_PITCH + c * 16, klb + (size_t)(k0 + r) * QKD + c * 8);
        }
#pragma unroll
        for (int i = 0; i < 8; i++) {
            int e = tid + i * 128;        // 1024 chunks per half
            int r = e >> 4, c = e & 15;
            CP_ASYNC16(vst + r * V_PITCH + c * 16, vhb + (size_t)(k0 + r) * VDIM + c * 8);
            CP_ASYNC16(vst + V_HALF + r * V_PITCH + c * 16, vlb + (size_t)(k0 + r) * VDIM + c * 8);
        }
    };

    load_kv(0, 0);
    CP_COMMIT();                          // group: Q + tile0

    // fragment addressing (same proven patterns as mma_gemm)
    int a_r = w * 16 + (lane & 15);
    int a_c8 = (lane >> 4) << 3;
    int b_r = ((lane >> 4) << 3) + (lane & 7);   // + nb*16
    int b_c8 = ((lane >> 3) & 1) << 3;
    int vt_r = lane & 15;                        // + kk*16 (trans)
    int vt_c8 = (lane >> 4) << 3;                // + j2*16

    int g = lane >> 2, t4 = lane & 3;

    float m0 = -INFINITY, m1 = -INFINITY, l0 = 0.f, l1 = 0.f;
    float O[16][4];
#pragma unroll
    for (int j = 0; j < 16; j++)
#pragma unroll
        for (int k = 0; k < 4; k++) O[j][k] = 0.f;

    int qrow0 = q0 + w * 16 + g;
    int qrow1 = qrow0 + 8;

    for (int kt = 0; kt <= qt; kt++) {
        int s = kt & 1;
        if (kt + 1 <= qt) { load_kv(kt + 1, s ^ 1); CP_COMMIT(); CP_WAIT1(); }
        else              { CP_WAIT0(); }
        __syncthreads();

        uint32_t kst = sb + OFF_K + s * (2 * K_HALF);
        uint32_t vst = sb + OFF_V + s * (2 * V_HALF);

        // ---- QK^T: 64x64 scores (warp: 16x64) ----
        float sc[8][4];
#pragma unroll
        for (int j = 0; j < 8; j++)
#pragma unroll
            for (int k = 0; k < 4; k++) sc[j][k] = 0.f;

#pragma unroll
        for (int kk = 0; kk < 12; kk++) {
            uint32_t ah[4], al[4];
            uint32_t aoff = (uint32_t)(a_r * KQ_PITCH + (kk * 16 + a_c8) * 2);
            LDSM4(ah, sb + OFF_Q + aoff);
            LDSM4(al, sb + OFF_Q + Q_HALF + aoff);
#pragma unroll
            for (int nb = 0; nb < 4; nb++) {
                uint32_t bhf[4], blf[4];
                uint32_t boff = (uint32_t)((nb * 16 + b_r) * KQ_PITCH + (kk * 16 + b_c8) * 2);
                LDSM4(bhf, kst + boff);
                LDSM4(blf, kst + K_HALF + boff);
                MMA16816(sc[2*nb],   ah, bhf[0], bhf[1]);
                MMA16816(sc[2*nb],   ah, blf[0], blf[1]);
                MMA16816(sc[2*nb],   al, bhf[0], bhf[1]);
                MMA16816(sc[2*nb+1], ah, bhf[2], bhf[3]);
                MMA16816(sc[2*nb+1], ah, blf[2], blf[3]);
                MMA16816(sc[2*nb+1], al, bhf[2], bhf[3]);
            }
        }

        // ---- mask (diagonal tile only) ----
        if (kt == qt) {
            int k0 = kt * 64;
#pragma unroll
            for (int j = 0; j < 8; j++) {
                int col = k0 + j * 8 + t4 * 2;
                if (col     > qrow0) sc[j][0] = -INFINITY;
                if (col + 1 > qrow0) sc[j][1] = -INFINITY;
                if (col     > qrow1) sc[j][2] = -INFINITY;
                if (col + 1 > qrow1) sc[j][3] = -INFINITY;
            }
        }

        // ---- online softmax (rows g, g+8) ----
        float rm0 = -INFINITY, rm1 = -INFINITY;
#pragma unroll
        for (int j = 0; j < 8; j++) {
            rm0 = fmaxf(rm0, fmaxf(sc[j][0], sc[j][1]));
            rm1 = fmaxf(rm1, fmaxf(sc[j][2], sc[j][3]));
        }
        rm0 = fmaxf(rm0, __shfl_xor_sync(0xffffffffu, rm0, 1));
        rm0 = fmaxf(rm0, __shfl_xor_sync(0xffffffffu, rm0, 2));
        rm1 = fmaxf(rm1, __shfl_xor_sync(0xffffffffu, rm1, 1));
        rm1 = fmaxf(rm1, __shfl_xor_sync(0xffffffffu, rm1, 2));
        float nm0 = fmaxf(m0, rm0), nm1 = fmaxf(m1, rm1);
        float rs0 = 0.f, rs1 = 0.f;
#pragma unroll
        for (int j = 0; j < 8; j++) {
            sc[j][0] = __expf(sc[j][0] - nm0);
            sc[j][1] = __expf(sc[j][1] - nm0);
            sc[j][2] = __expf(sc[j][2] - nm1);
            sc[j][3] = __expf(sc[j][3] - nm1);
            rs0 += sc[j][0] + sc[j][1];
            rs1 += sc[j][2] + sc[j][3];
        }
        rs0 += __shfl_xor_sync(0xffffffffu, rs0, 1);
        rs0 += __shfl_xor_sync(0xffffffffu, rs0, 2);
        rs1 += __shfl_xor_sync(0xffffffffu, rs1, 1);
        rs1 += __shfl_xor_sync(0xffffffffu, rs1, 2);
        float al0 = __expf(m0 - nm0), al1 = __expf(m1 - nm1);
        l0 = l0 * al0 + rs0; l1 = l1 * al1 + rs1;
        m0 = nm0; m1 = nm1;
#pragma unroll
        for (int j = 0; j < 16; j++) {
            O[j][0] *= al0; O[j][1] *= al0;
            O[j][2] *= al1; O[j][3] *= al1;
        }

        // ---- convert P to bf16 hi/lo fragments ----
        uint32_t ph2[8][2], pl2[8][2];
#pragma unroll
        for (int j = 0; j < 8; j++) {
            float h0 = 0.f, h1 = 0.f, h2 = 0.f, h3 = 0.f;
            __nv_bfloat162 p01 = __floats2bfloat162_rn(sc[j][0], sc[j][1]);
            __nv_bfloat162 p23 = __floats2bfloat162_rn(sc[j][2], sc[j][3]);
            ph2[j][0] = *(uint32_t*)&p01;
            ph2[j][1] = *(uint32_t*)&p23;
            h0 = sc[j][0] - __bfloat162float(p01.x);
            h1 = sc[j][1] - __bfloat162float(p01.y);
            h2 = sc[j][2] - __bfloat162float(p23.x);
            h3 = sc[j][3] - __bfloat162float(p23.y);
            __nv_bfloat162 q01 = __floats2bfloat162_rn(h0, h1);
            __nv_bfloat162 q23 = __floats2bfloat162_rn(h2, h3);
            pl2[j][0] = *(uint32_t*)&q01;
            pl2[j][1] = *(uint32_t*)&q23;
        }

        // ---- O += P @ V (warp: 16x128) ----
#pragma unroll
        for (int kk = 0; kk < 4; kk++) {
            uint32_t ah[4] = { ph2[2*kk][0], ph2[2*kk][1], ph2[2*kk+1][0], ph2[2*kk+1][1] };
            uint32_t al[4] = { pl2[2*kk][0], pl2[2*kk][1], pl2[2*kk+1][0], pl2[2*kk+1][1] };
#pragma unroll
            for (int j2 = 0; j2 < 8; j2++) {
                uint32_t vhf[4], vlf[4];
                uint32_t voff = (uint32_t)((kk * 16 + vt_r) * V_PITCH + (j2 * 16 + vt_c8) * 2);
                LDSM4T(vhf, vst + voff);
                LDSM4T(vlf, vst + V_HALF + voff);
                MMA16816(O[2*j2],   ah, vhf[0], vhf[1]);
                MMA16816(O[2*j2],   al, vhf[0], vhf[1]);
                MMA16816(O[2*j2],   ah, vlf[0], vlf[1]);
                MMA16816(O[2*j2+1], ah, vhf[2], vhf[3]);
                MMA16816(O[2*j2+1], al, vhf[2], vhf[3]);
                MMA16816(O[2*j2+1], ah, vlf[2], vlf[3]);
            }
        }
        __syncthreads();
    }

    // ---- epilogue ----
    float inv0 = 1.f / l0, inv1 = 1.f / l1;
    float* ob0 = out + ((size_t)(b * Ss + qrow0)) * (NHh * VDIM) + h * VDIM;
    float* ob1 = out + ((size_t)(b * Ss + qrow1)) * (NHh * VDIM) + h * VDIM;
#pragma unroll
    for (int j = 0; j < 16; j++) {
        int d = j * 8 + t4 * 2;
        *(float2*)(ob0 + d) = make_float2(O[j][0] * inv0, O[j][1] * inv0);
        *(float2*)(ob1 + d) = make_float2(O[j][2] * inv1, O[j][3] * inv1);
    }
}

// ================= launch =================
extern "C" void kernel_launch(void* const* d_in, const int* in_sizes, int n_in,
                              void* d_out, int out_size) {
    const float* hs     = (const float*)d_in[0];
    const int*   pos    = (const int*)  d_in[1];
    const float* w_q_a  = (const float*)d_in[3];
    const float* q_ln   = (const float*)d_in[4];
    const float* w_q_b  = (const float*)d_in[5];
    const float* w_kv_a = (const float*)d_in[6];
    const float* kv_ln  = (const float*)d_in[7];
    const float* w_kv_b = (const float*)d_in[8];
    const float* w_o    = (const float*)d_in[9];
    float* out = (float*)d_out;

    float *qc, *q, *kvt, *kvc, *krope, *kvp, *attn;
    cudaGetSymbolAddress((void**)&qc,    g_qc);
    cudaGetSymbolAddress((void**)&q,     g_q);
    cudaGetSymbolAddress((void**)&kvt,   g_kvt);
    cudaGetSymbolAddress((void**)&kvc,   g_kvc);
    cudaGetSymbolAddress((void**)&krope, g_krope);
    cudaGetSymbolAddress((void**)&kvp,   g_kv);
    cudaGetSymbolAddress((void**)&attn,  g_attn);

    __nv_bfloat16 *hs_h,*hs_l,*qc_h,*qc_l,*kvc_h,*kvc_l,*at_h,*at_l;
    __nv_bfloat16 *wqa_h,*wqa_l,*wqb_h,*wqb_l,*wkva_h,*wkva_l,*wkvb_h,*wkvb_l,*wo_h,*wo_l;
    __nv_bfloat16 *qfh,*qfl,*kfh,*kfl,*vfh,*vfl;
    cudaGetSymbolAddress((void**)&hs_h,  g_hs_h);  cudaGetSymbolAddress((void**)&hs_l,  g_hs_l);
    cudaGetSymbolAddress((void**)&qc_h,  g_qc_h);  cudaGetSymbolAddress((void**)&qc_l,  g_qc_l);
    cudaGetSymbolAddress((void**)&kvc_h, g_kvc_h); cudaGetSymbolAddress((void**)&kvc_l, g_kvc_l);
    cudaGetSymbolAddress((void**)&at_h,  g_at_h);  cudaGetSymbolAddress((void**)&at_l,  g_at_l);
    cudaGetSymbolAddress((void**)&wqa_h, g_wqa_h); cudaGetSymbolAddress((void**)&wqa_l, g_wqa_l);
    cudaGetSymbolAddress((void**)&wqb_h, g_wqb_h); cudaGetSymbolAddress((void**)&wqb_l, g_wqb_l);
    cudaGetSymbolAddress((void**)&wkva_h,g_wkva_h);cudaGetSymbolAddress((void**)&wkva_l,g_wkva_l);
    cudaGetSymbolAddress((void**)&wkvb_h,g_wkvb_h);cudaGetSymbolAddress((void**)&wkvb_l,g_wkvb_l);
    cudaGetSymbolAddress((void**)&wo_h,  g_wo_h);  cudaGetSymbolAddress((void**)&wo_l,  g_wo_l);
    cudaGetSymbolAddress((void**)&qfh,   g_qfh);   cudaGetSymbolAddress((void**)&qfl,   g_qfl);
    cudaGetSymbolAddress((void**)&kfh,   g_kfh);   cudaGetSymbolAddress((void**)&kfl,   g_kfl);
    cudaGetSymbolAddress((void**)&vfh,   g_vfh);   cudaGetSymbolAddress((void**)&vfl,   g_vfl);

    cudaFuncSetAttribute(mma_gemm, cudaFuncAttributeMaxDynamicSharedMemorySize, GEMM_SMEM);
    cudaFuncSetAttribute(flash_mma, cudaFuncAttributeMaxDynamicSharedMemorySize, FLASH_SMEM);

    dim3 tb(32, 8);

    transpose_split<<<dim3(QLORA/32, HID/32), tb>>>(w_q_a, wqa_h, wqa_l, HID, QLORA);
    transpose_split<<<dim3((NHh*QKD)/32, QLORA/32), tb>>>(w_q_b, wqb_h, wqb_l, QLORA, NHh*QKD);
    transpose_split<<<dim3(WKVA_NPAD/32, HID/32), tb>>>(w_kv_a, wkva_h, wkva_l, HID, KVLORA+ROPED);
    transpose_split<<<dim3((NHh*(NOPE+VDIM))/32, KVLORA/32), tb>>>(w_kv_b, wkvb_h, wkvb_l, KVLORA, NHh*(NOPE+VDIM));
    transpose_split<<<dim3(HID/32, (NHh*VDIM)/32), tb>>>(w_o, wo_h, wo_l, NHh*VDIM, HID);
    convert_split<<<(ROWS*(size_t)HID/4 + 255)/256, 256>>>(hs, hs_h, hs_l, (size_t)ROWS*HID);

    // G1: qc = hs @ w_q_a
    mma_gemm<<<dim3(QLORA/128, ROWS/128), 256, GEMM_SMEM>>>(hs_h, hs_l, wqa_h, wqa_l, qc, ROWS, QLORA, HID);
    rmsnorm_rows<<<ROWS, 256>>>(qc, q_ln, QLORA);
    convert_split<<<(ROWS*(size_t)QLORA/4 + 255)/256, 256>>>(qc, qc_h, qc_l, (size_t)ROWS*QLORA);

    // G2: q = qc @ w_q_b
    mma_gemm<<<dim3((NHh*QKD)/128, ROWS/128), 256, GEMM_SMEM>>>(qc_h, qc_l, wqb_h, wqb_l, q, ROWS, NHh*QKD, QLORA);

    // G3: kvt = hs @ w_kv_a
    mma_gemm<<<dim3(WKVA_NPAD/128, ROWS/128), 256, GEMM_SMEM>>>(hs_h, hs_l, wkva_h, wkva_l, kvt, ROWS, KVLORA+ROPED, HID);

    kv_split<<<ROWS, 256>>>(kvt, kv_ln, pos, kvc, krope);
    convert_split<<<(ROWS*(size_t)KVLORA/4 + 255)/256, 256>>>(kvc, kvc_h, kvc_l, (size_t)ROWS*KVLORA);
    rope_q<<<ROWS, 512>>>(q, pos);

    // G4: kv = kvc @ w_kv_b
    mma_gemm<<<dim3((NHh*(NOPE+VDIM))/128, ROWS/128), 256, GEMM_SMEM>>>(kvc_h, kvc_l, wkvb_h, wkvb_l, kvp, ROWS, NHh*(NOPE+VDIM), KVLORA);

    // flash prep + attention
    prep_q<<<ROWS, 256>>>(q, qfh, qfl);
    prep_kv<<<ROWS, 256>>>(kvp, krope, kfh, kfl, vfh, vfl);
    flash_mma<<<dim3(Ss/64, NHh, Bb), 128, FLASH_SMEM>>>(qfh, qfl, kfh, kfl, vfh, vfl, attn);
    convert_split<<<(ROWS*(size_t)(NHh*VDIM)/4 + 255)/256, 256>>>(attn, at_h, at_l, (size_t)ROWS*NHh*VDIM);

    // G5: out = attn @ w_o
    mma_gemm<<<dim3(HID/128, ROWS/128), 256, GEMM_SMEM>>>(at_h, at_l, wo_h, wo_l, out, ROWS, HID, HID);
}

// round 5
// speedup vs baseline: 2.7146x; 1.0377x over previous
#include <cuda_runtime.h>
#include <cuda_bf16.h>
#include <math.h>
#include <cstdint>

// ---------------- problem constants ----------------
#define Bb   2
#define Ss   2048
#define HID  2048
#define NHh  16
#define QLORA 1536
#define KVLORA 512
#define NOPE 128
#define ROPED 64
#define VDIM 128
#define QKD  192
#define ROWS (Bb*Ss)          // 4096
#define WKVA_NPAD 640
#define SCALEF 0.07216878364870322f

// ---------------- fp32 scratch ----------------
__device__ float g_qc   [(size_t)ROWS * QLORA];
__device__ float g_q    [(size_t)ROWS * NHh * QKD];
__device__ float g_kvt  [(size_t)ROWS * (KVLORA+ROPED)];

// ---------------- bf16 split scratch (activations) ----------------
__device__ __nv_bfloat16 g_hs_h [(size_t)ROWS*HID],    g_hs_l [(size_t)ROWS*HID];
__device__ __nv_bfloat16 g_qc_h [(size_t)ROWS*QLORA],  g_qc_l [(size_t)ROWS*QLORA];
__device__ __nv_bfloat16 g_kvc_h[(size_t)ROWS*KVLORA], g_kvc_l[(size_t)ROWS*KVLORA];
__device__ __nv_bfloat16 g_at_h [(size_t)ROWS*NHh*VDIM], g_at_l[(size_t)ROWS*NHh*VDIM];

// ---------------- bf16 split scratch (transposed weights, [N,K]) ----------
__device__ __nv_bfloat16 g_wqa_h [(size_t)QLORA*HID],            g_wqa_l [(size_t)QLORA*HID];
__device__ __nv_bfloat16 g_wqb_h [(size_t)(NHh*QKD)*QLORA],      g_wqb_l [(size_t)(NHh*QKD)*QLORA];
__device__ __nv_bfloat16 g_wkva_h[(size_t)WKVA_NPAD*HID],        g_wkva_l[(size_t)WKVA_NPAD*HID];
__device__ __nv_bfloat16 g_wkvb_h[(size_t)(NHh*(NOPE+VDIM))*KVLORA], g_wkvb_l[(size_t)(NHh*(NOPE+VDIM))*KVLORA];
__device__ __nv_bfloat16 g_wo_h  [(size_t)HID*(NHh*VDIM)],       g_wo_l  [(size_t)HID*(NHh*VDIM)];

// ---------------- flash bf16 buffers, [b,h,s,d] contiguous ----------
__device__ __nv_bfloat16 g_qfh[(size_t)ROWS*NHh*QKD], g_qfl[(size_t)ROWS*NHh*QKD];
__device__ __nv_bfloat16 g_kfh[(size_t)ROWS*NHh*QKD], g_kfl[(size_t)ROWS*NHh*QKD];
__device__ __nv_bfloat16 g_vfh[(size_t)ROWS*NHh*VDIM], g_vfl[(size_t)ROWS*NHh*VDIM];

// ================= helpers =================
__device__ __forceinline__ uint32_t smem_u32(const void* p) {
    uint32_t a;
    asm("{ .reg .u64 t; cvta.to.shared.u64 t, %1; cvt.u32.u64 %0, t; }" : "=r"(a) : "l"(p));
    return a;
}

#define LDSM4(r, a) asm volatile( \
    "ldmatrix.sync.aligned.m8n8.x4.shared.b16 {%0,%1,%2,%3}, [%4];" \
    : "=r"((r)[0]),"=r"((r)[1]),"=r"((r)[2]),"=r"((r)[3]) : "r"(a))

#define LDSM4T(r, a) asm volatile( \
    "ldmatrix.sync.aligned.m8n8.x4.trans.shared.b16 {%0,%1,%2,%3}, [%4];" \
    : "=r"((r)[0]),"=r"((r)[1]),"=r"((r)[2]),"=r"((r)[3]) : "r"(a))

#define MMA16816(d, a, b0v, b1v) asm volatile( \
    "mma.sync.aligned.m16n8k16.row.col.f32.bf16.bf16.f32 " \
    "{%0,%1,%2,%3},{%4,%5,%6,%7},{%8,%9},{%0,%1,%2,%3};" \
    : "+f"((d)[0]),"+f"((d)[1]),"+f"((d)[2]),"+f"((d)[3]) \
    : "r"((a)[0]),"r"((a)[1]),"r"((a)[2]),"r"((a)[3]), "r"(b0v),"r"(b1v))

#define CP_ASYNC16(sa, ga) asm volatile( \
    "cp.async.cg.shared.global [%0], [%1], 16;" :: "r"(sa), "l"(ga))
#define CP_COMMIT() asm volatile("cp.async.commit_group;" ::: "memory")
#define CP_WAIT1()  asm volatile("cp.async.wait_group 1;" ::: "memory")
#define CP_WAIT0()  asm volatile("cp.async.wait_group 0;" ::: "memory")

__device__ __forceinline__ void split_hl(float v, __nv_bfloat16& h, __nv_bfloat16& l) {
    h = __float2bfloat16(v);
    l = __float2bfloat16(v - __bfloat162float(h));
}

// ================= bf16x2 HMMA GEMM, 3-stage pipeline =================
// C[M,N] = A[M,K] @ Bt[N,K]^T, hi/lo split, 3 MMA passes.
// MODE 0: fp32 C.  MODE 1: scatter epilogue -> kfh/kfl (d<128) | vfh/vfl.
#define BK 32
#define PITCH 40
#define TILE_B (128*PITCH*2)
#define STAGE_B (4*TILE_B)            // 40960
#define NSTAGE 3
#define GEMM_SMEM (NSTAGE*STAGE_B)    // 122880

template<int MODE>
__global__ void __launch_bounds__(256, 1) mma_gemm_t(
    const __nv_bfloat16* __restrict__ Ah, const __nv_bfloat16* __restrict__ Al,
    const __nv_bfloat16* __restrict__ Bh, const __nv_bfloat16* __restrict__ Bl,
    float* __restrict__ C,
    __nv_bfloat16* __restrict__ P0, __nv_bfloat16* __restrict__ P1,
    __nv_bfloat16* __restrict__ P2, __nv_bfloat16* __restrict__ P3,
    int M, int N, int K) {
    extern __shared__ char sm[];
    uint32_t sbase = smem_u32(sm);

    int tid = threadIdx.x, lane = tid & 31, wid = tid >> 5;
    int warpM = wid & 3, warpN = wid >> 2;
    int row0 = blockIdx.y * 128, col0 = blockIdx.x * 128;

    const __nv_bfloat16* gsrc[4] = {
        Ah + (size_t)row0 * K, Al + (size_t)row0 * K,
        Bh + (size_t)col0 * K, Bl + (size_t)col0 * K };

    auto issue_loads = [&](int c, int s) {
        int k0 = c * BK;
        uint32_t st = sbase + s * STAGE_B;
#pragma unroll
        for (int t = 0; t < 4; t++) {
#pragma unroll
            for (int j = 0; j < 2; j++) {
                int seg = tid + j * 256;
                int r = seg >> 2, cc = seg & 3;
                const __nv_bfloat16* g = gsrc[t] + (size_t)r * K + k0 + cc * 8;
                uint32_t sa = st + t * TILE_B + r * (PITCH * 2) + cc * 16;
                CP_ASYNC16(sa, g);
            }
        }
        CP_COMMIT();
    };

    float acc[2][8][4];
#pragma unroll
    for (int i = 0; i < 2; i++)
#pragma unroll
        for (int j = 0; j < 8; j++)
#pragma unroll
            for (int k = 0; k < 4; k++) acc[i][j][k] = 0.f;

    int a_r = warpM * 32 + (lane & 15);
    int a_c8 = (lane >> 4) << 3;
    int b_r = warpN * 64 + ((lane >> 4) << 3) + (lane & 7);
    int b_c8 = ((lane >> 3) & 1) << 3;

    auto compute = [&](int s) {
        uint32_t st = sbase + s * STAGE_B;
#pragma unroll
        for (int ki = 0; ki < 2; ki++) {
            uint32_t ah[2][4], al[2][4];
#pragma unroll
            for (int mi = 0; mi < 2; mi++) {
                uint32_t off = (uint32_t)((a_r + mi * 16) * (PITCH * 2) + (ki * 16 + a_c8) * 2);
                LDSM4(ah[mi], st + off);
                LDSM4(al[mi], st + TILE_B + off);
            }
            uint32_t bh[4][4], bl[4][4];
#pragma unroll
            for (int nb = 0; nb < 4; nb++) {
                uint32_t off = (uint32_t)((b_r + nb * 16) * (PITCH * 2) + (ki * 16 + b_c8) * 2);
                LDSM4(bh[nb], st + 2 * TILE_B + off);
                LDSM4(bl[nb], st + 3 * TILE_B + off);
            }
#pragma unroll
            for (int mi = 0; mi < 2; mi++)
#pragma unroll
                for (int nb = 0; nb < 4; nb++) {
                    MMA16816(acc[mi][2*nb],   ah[mi], bh[nb][0], bh[nb][1]);
                    MMA16816(acc[mi][2*nb],   ah[mi], bl[nb][0], bl[nb][1]);
                    MMA16816(acc[mi][2*nb],   al[mi], bh[nb][0], bh[nb][1]);
                    MMA16816(acc[mi][2*nb+1], ah[mi], bh[nb][2], bh[nb][3]);
                    MMA16816(acc[mi][2*nb+1], ah[mi], bl[nb][2], bl[nb][3]);
                    MMA16816(acc[mi][2*nb+1], al[mi], bh[nb][2], bh[nb][3]);
                }
        }
    };

    int nc = K / BK;
    issue_loads(0, 0);
    issue_loads(1, 1);
    for (int c = 0; c < nc; c++) {
        int s = c % NSTAGE;
        if (c + 1 < nc) { CP_WAIT1(); } else { CP_WAIT0(); }
        __syncthreads();
        if (c + 2 < nc) issue_loads(c + 2, (c + 2) % NSTAGE);
        compute(s);
    }

    int g = lane >> 2, t = lane & 3;
    if (MODE == 0) {
#pragma unroll
        for (int mi = 0; mi < 2; mi++)
#pragma unroll
            for (int n8 = 0; n8 < 8; n8++) {
                int col = col0 + warpN * 64 + n8 * 8 + t * 2;
                if (col < N) {
                    int r0 = row0 + warpM * 32 + mi * 16 + g;
                    float* p0 = C + (size_t)r0 * N + col;
                    p0[0] = acc[mi][n8][0]; p0[1] = acc[mi][n8][1];
                    float* p1 = p0 + (size_t)8 * N;
                    p1[0] = acc[mi][n8][2]; p1[1] = acc[mi][n8][3];
                }
            }
    } else {
        // MODE 1: N=4096, col = h*256 + dd; dd<128 -> K-nope (P0/P1, stride QKD),
        // dd>=128 -> V (P2/P3, stride VDIM). Whole CTA col-block is one region.
        int hH = col0 >> 8;
        int isV = (col0 >> 7) & 1;
        __nv_bfloat16* Dh = isV ? P2 : P0;
        __nv_bfloat16* Dl = isV ? P3 : P1;
        int stride = isV ? VDIM : QKD;
#pragma unroll
        for (int mi = 0; mi < 2; mi++)
#pragma unroll
            for (int n8 = 0; n8 < 8; n8++) {
                int col = col0 + warpN * 64 + n8 * 8 + t * 2;
                int d = col & 127;
#pragma unroll
                for (int rr = 0; rr < 2; rr++) {
                    int r0 = row0 + warpM * 32 + mi * 16 + g + rr * 8;
                    int b = r0 >> 11, srow = r0 & 2047;
                    size_t o = ((size_t)(b * NHh + hH) * Ss + srow) * stride + d;
                    __nv_bfloat16 h0, l0v, h1, l1v;
                    split_hl(acc[mi][n8][rr*2],   h0, l0v);
                    split_hl(acc[mi][n8][rr*2+1], h1, l1v);
                    *(__nv_bfloat162*)(Dh + o) = __nv_bfloat162(h0, h1);
                    *(__nv_bfloat162*)(Dl + o) = __nv_bfloat162(l0v, l1v);
                }
            }
    }
}

// ================= conversion / transpose kernels =================
__global__ void convert_split(const float* __restrict__ x, __nv_bfloat16* __restrict__ h,
                              __nv_bfloat16* __restrict__ l, size_t n) {
    size_t i = ((size_t)blockIdx.x * 256 + threadIdx.x) * 4;
    if (i >= n) return;
    float4 v = *(const float4*)(x + i);
    float a[4] = {v.x, v.y, v.z, v.w};
    __nv_bfloat16 hh[4], ll[4];
#pragma unroll
    for (int j = 0; j < 4; j++) split_hl(a[j], hh[j], ll[j]);
    *(__nv_bfloat162*)(h + i)     = __nv_bfloat162(hh[0], hh[1]);
    *(__nv_bfloat162*)(h + i + 2) = __nv_bfloat162(hh[2], hh[3]);
    *(__nv_bfloat162*)(l + i)     = __nv_bfloat162(ll[0], ll[1]);
    *(__nv_bfloat162*)(l + i + 2) = __nv_bfloat162(ll[2], ll[3]);
}

__global__ void transpose_split(const float* __restrict__ W, __nv_bfloat16* __restrict__ Th,
                                __nv_bfloat16* __restrict__ Tl, int K, int N) {
    __shared__ float tile[32][33];
    int n0 = blockIdx.x * 32, k0 = blockIdx.y * 32;
    int tx = threadIdx.x, ty = threadIdx.y;
#pragma unroll
    for (int i = 0; i < 4; i++) {
        int k = k0 + ty + i * 8, n = n0 + tx;
        tile[ty + i * 8][tx] = (n < N) ? W[(size_t)k * N + n] : 0.f;
    }
    __syncthreads();
#pragma unroll
    for (int i = 0; i < 4; i++) {
        int n = n0 + ty + i * 8;
        float v = tile[tx][ty + i * 8];
        __nv_bfloat16 h, l;
        split_hl(v, h, l);
        Th[(size_t)n * K + k0 + tx] = h;
        Tl[(size_t)n * K + k0 + tx] = l;
    }
}

// ================= fused rmsnorm -> hi/lo =================
__global__ void rmsnorm_split(const float* __restrict__ x, const float* __restrict__ w,
                              __nv_bfloat16* __restrict__ oh, __nv_bfloat16* __restrict__ ol,
                              int L) {
    __shared__ float red[256];
    int tid = threadIdx.x;
    const float* r = x + (size_t)blockIdx.x * L;
    float ss = 0.f;
    for (int i = tid; i < L; i += 256) { float v = r[i]; ss += v * v; }
    red[tid] = ss; __syncthreads();
    for (int s = 128; s > 0; s >>= 1) { if (tid < s) red[tid] += red[tid + s]; __syncthreads(); }
    float scale = rsqrtf(red[0] / (float)L + 1e-6f);
    for (int i = tid; i < L; i += 256) {
        __nv_bfloat16 h, l;
        split_hl(r[i] * scale * w[i], h, l);
        oh[(size_t)blockIdx.x * L + i] = h;
        ol[(size_t)blockIdx.x * L + i] = l;
    }
}

// ================= fused kv split: rmsnorm->hi/lo, rope->K final layout ======
__global__ void kv_split2(const float* __restrict__ kvt, const float* __restrict__ w,
                          const int* __restrict__ pos,
                          __nv_bfloat16* __restrict__ kvch, __nv_bfloat16* __restrict__ kvcl,
                          __nv_bfloat16* __restrict__ kfh, __nv_bfloat16* __restrict__ kfl) {
    __shared__ float red[256];
    __shared__ float rop[64];
    int tid = threadIdx.x, row = blockIdx.x;
    const float* r = kvt + (size_t)row * (KVLORA + ROPED);
    float ss = 0.f;
    for (int i = tid; i < KVLORA; i += 256) { float v = r[i]; ss += v * v; }
    red[tid] = ss; __syncthreads();
    for (int s = 128; s > 0; s >>= 1) { if (tid < s) red[tid] += red[tid + s]; __syncthreads(); }
    float scale = rsqrtf(red[0] / (float)KVLORA + 1e-6f);
    for (int i = tid; i < KVLORA; i += 256) {
        __nv_bfloat16 h, l;
        split_hl(r[i] * scale * w[i], h, l);
        kvch[(size_t)row * KVLORA + i] = h;
        kvcl[(size_t)row * KVLORA + i] = l;
    }
    if (tid < 32) {
        float p = (float)pos[row];
        float inv_freq = powf(10000.f, -(float)tid / 32.f);
        float ang = p * inv_freq;
        float c = cosf(ang), s = sinf(ang);
        float x1 = r[KVLORA + tid];
        float x2 = r[KVLORA + 32 + tid];
        rop[tid]      = x1 * c - x2 * s;
        rop[tid + 32] = x2 * c + x1 * s;
    }
    __syncthreads();
    int b = row >> 11, srow = row & 2047;
    for (int e = tid; e < NHh * ROPED; e += 256) {
        int h = e >> 6, d = e & 63;
        __nv_bfloat16 hh, ll;
        split_hl(rop[d], hh, ll);
        size_t o = ((size_t)(b * NHh + h) * Ss + srow) * QKD + NOPE + d;
        kfh[o] = hh;
        kfl[o] = ll;
    }
}

// ================= fused rope+scale+prep for Q =================
__global__ void rope_prep_q(const float* __restrict__ q, const int* __restrict__ pos,
                            __nv_bfloat16* __restrict__ qfh, __nv_bfloat16* __restrict__ qfl) {
    int row = blockIdx.x;
    int b = row >> 11, srow = row & 2047;
    float p = (float)pos[row];
    const float* qr = q + (size_t)row * (NHh * QKD);
    for (int e = threadIdx.x; e < NHh * QKD; e += 256) {
        int h = e / QKD, d = e % QKD;
        float v;
        if (d < NOPE) v = qr[e];
        else {
            int i = d - NOPE;
            int j = i & 31;
            float inv_freq = powf(10000.f, -(float)j / 32.f);
            float ang = p * inv_freq;
            float c = cosf(ang), s = sinf(ang);
            float x1 = qr[h * QKD + NOPE + j];
            float x2 = qr[h * QKD + NOPE + 32 + j];
            v = (i < 32) ? (x1 * c - x2 * s) : (x2 * c + x1 * s);
        }
        v *= SCALEF;
        __nv_bfloat16 hh, ll;
        split_hl(v, hh, ll);
        size_t o = ((size_t)(b * NHh + h) * Ss + srow) * QKD + d;
        qfh[o] = hh;
        qfl[o] = ll;
    }
}

// ================= tensor-core flash attention =================
#define KQ_PITCH 400
#define V_PITCH  272
#define Q_HALF   (64*KQ_PITCH)
#define K_HALF   (64*KQ_PITCH)
#define V_HALF   (64*V_PITCH)
#define OFF_Q    0
#define OFF_K    (2*Q_HALF)
#define OFF_V    (OFF_K + 4*K_HALF)
#define FLASH_SMEM (OFF_V + 4*V_HALF)   // 223232

__global__ void __launch_bounds__(128, 1) flash_mma(
    const __nv_bfloat16* __restrict__ qh, const __nv_bfloat16* __restrict__ ql,
    const __nv_bfloat16* __restrict__ kh, const __nv_bfloat16* __restrict__ kl,
    const __nv_bfloat16* __restrict__ vh, const __nv_bfloat16* __restrict__ vl,
    __nv_bfloat16* __restrict__ oh, __nv_bfloat16* __restrict__ ol) {
    extern __shared__ char sm[];
    uint32_t sb = smem_u32(sm);

    int qt = blockIdx.x, h = blockIdx.y, b = blockIdx.z;
    int q0 = qt * 64;
    int tid = threadIdx.x, lane = tid & 31, w = tid >> 5;
    int bh = b * NHh + h;

    const __nv_bfloat16* qhb = qh + ((size_t)bh * Ss + q0) * QKD;
    const __nv_bfloat16* qlb = ql + ((size_t)bh * Ss + q0) * QKD;
    const __nv_bfloat16* khb = kh + (size_t)bh * Ss * QKD;
    const __nv_bfloat16* klb = kl + (size_t)bh * Ss * QKD;
    const __nv_bfloat16* vhb = vh + (size_t)bh * Ss * VDIM;
    const __nv_bfloat16* vlb = vl + (size_t)bh * Ss * VDIM;

#pragma unroll
    for (int i = 0; i < 12; i++) {
        int e = tid + i * 128;
        int r = e / 24, c = e % 24;
        CP_ASYNC16(sb + OFF_Q + r * KQ_PITCH + c * 16, qhb + (size_t)r * QKD + c * 8);
        CP_ASYNC16(sb + OFF_Q + Q_HALF + r * KQ_PITCH + c * 16, qlb + (size_t)r * QKD + c * 8);
    }

    auto load_kv = [&](int kt, int s) {
        int k0 = kt * 64;
        uint32_t kst = sb + OFF_K + s * (2 * K_HALF);
        uint32_t vst = sb + OFF_V + s * (2 * V_HALF);
#pragma unroll
        for (int i = 0; i < 12; i++) {
            int e = tid + i * 128;
            int r = e / 24, c = e % 24;
            CP_ASYNC16(kst + r * KQ_PITCH + c * 16, khb + (size_t)(k0 + r) * QKD + c * 8);
            CP_ASYNC16(kst + K_HALF + r * KQ_PITCH + c * 16, klb + (size_t)(k0 + r) * QKD + c * 8);
        }
#pragma unroll
        for (int i = 0; i < 8; i++) {
            int e = tid + i * 128;
            int r = e >> 4, c = e & 15;
            CP_ASYNC16(vst + r * V_PITCH + c * 16, vhb + (size_t)(k0 + r) * VDIM + c * 8);
            CP_ASYNC16(vst + V_HALF + r * V_PITCH + c * 16, vlb + (size_t)(k0 + r) * VDIM + c * 8);
        }
    };

    load_kv(0, 0);
    CP_COMMIT();

    int a_r = w * 16 + (lane & 15);
    int a_c8 = (lane >> 4) << 3;
    int b_r = ((lane >> 4) << 3) + (lane & 7);
    int b_c8 = ((lane >> 3) & 1) << 3;
    int vt_r = lane & 15;
    int vt_c8 = (lane >> 4) << 3;

    int g = lane >> 2, t4 = lane & 3;

    float m0 = -INFINITY, m1 = -INFINITY, l0 = 0.f, l1 = 0.f;
    float O[16][4];
#pragma unroll
    for (int j = 0; j < 16; j++)
#pragma unroll
        for (int k = 0; k < 4; k++) O[j][k] = 0.f;

    int qrow0 = q0 + w * 16 + g;
    int qrow1 = qrow0 + 8;

    for (int kt = 0; kt <= qt; kt++) {
        int s = kt & 1;
        if (kt + 1 <= qt) { load_kv(kt + 1, s ^ 1); CP_COMMIT(); CP_WAIT1(); }
        else              { CP_WAIT0(); }
        __syncthreads();

        uint32_t kst = sb + OFF_K + s * (2 * K_HALF);
        uint32_t vst = sb + OFF_V + s * (2 * V_HALF);

        float sc[8][4];
#pragma unroll
        for (int j = 0; j < 8; j++)
#pragma unroll
            for (int k = 0; k < 4; k++) sc[j][k] = 0.f;

#pragma unroll
        for (int kk = 0; kk < 12; kk++) {
            uint32_t ah[4], al[4];
            uint32_t aoff = (uint32_t)(a_r * KQ_PITCH + (kk * 16 + a_c8) * 2);
            LDSM4(ah, sb + OFF_Q + aoff);
            LDSM4(al, sb + OFF_Q + Q_HALF + aoff);
#pragma unroll
            for (int nb = 0; nb < 4; nb++) {
                uint32_t bhf[4], blf[4];
                uint32_t boff = (uint32_t)((nb * 16 + b_r) * KQ_PITCH + (kk * 16 + b_c8) * 2);
                LDSM4(bhf, kst + boff);
                LDSM4(blf, kst + K_HALF + boff);
                MMA16816(sc[2*nb],   ah, bhf[0], bhf[1]);
                MMA16816(sc[2*nb],   ah, blf[0], blf[1]);
                MMA16816(sc[2*nb],   al, bhf[0], bhf[1]);
                MMA16816(sc[2*nb+1], ah, bhf[2], bhf[3]);
                MMA16816(sc[2*nb+1], ah, blf[2], blf[3]);
                MMA16816(sc[2*nb+1], al, bhf[2], bhf[3]);
            }
        }

        if (kt == qt) {
            int k0 = kt * 64;
#pragma unroll
            for (int j = 0; j < 8; j++) {
                int col = k0 + j * 8 + t4 * 2;
                if (col     > qrow0) sc[j][0] = -INFINITY;
                if (col + 1 > qrow0) sc[j][1] = -INFINITY;
                if (col     > qrow1) sc[j][2] = -INFINITY;
                if (col + 1 > qrow1) sc[j][3] = -INFINITY;
            }
        }

        float rm0 = -INFINITY, rm1 = -INFINITY;
#pragma unroll
        for (int j = 0; j < 8; j++) {
            rm0 = fmaxf(rm0, fmaxf(sc[j][0], sc[j][1]));
            rm1 = fmaxf(rm1, fmaxf(sc[j][2], sc[j][3]));
        }
        rm0 = fmaxf(rm0, __shfl_xor_sync(0xffffffffu, rm0, 1));
        rm0 = fmaxf(rm0, __shfl_xor_sync(0xffffffffu, rm0, 2));
        rm1 = fmaxf(rm1, __shfl_xor_sync(0xffffffffu, rm1, 1));
        rm1 = fmaxf(rm1, __shfl_xor_sync(0xffffffffu, rm1, 2));
        float nm0 = fmaxf(m0, rm0), nm1 = fmaxf(m1, rm1);
        float rs0 = 0.f, rs1 = 0.f;
#pragma unroll
        for (int j = 0; j < 8; j++) {
            sc[j][0] = __expf(sc[j][0] - nm0);
            sc[j][1] = __expf(sc[j][1] - nm0);
            sc[j][2] = __expf(sc[j][2] - nm1);
            sc[j][3] = __expf(sc[j][3] - nm1);
            rs0 += sc[j][0] + sc[j][1];
            rs1 += sc[j][2] + sc[j][3];
        }
        rs0 += __shfl_xor_sync(0xffffffffu, rs0, 1);
        rs0 += __shfl_xor_sync(0xffffffffu, rs0, 2);
        rs1 += __shfl_xor_sync(0xffffffffu, rs1, 1);
        rs1 += __shfl_xor_sync(0xffffffffu, rs1, 2);
        float al0 = __expf(m0 - nm0), al1 = __expf(m1 - nm1);
        l0 = l0 * al0 + rs0; l1 = l1 * al1 + rs1;
        m0 = nm0; m1 = nm1;
#pragma unroll
        for (int j = 0; j < 16; j++) {
            O[j][0] *= al0; O[j][1] *= al0;
            O[j][2] *= al1; O[j][3] *= al1;
        }

        uint32_t ph2[8][2], pl2[8][2];
#pragma unroll
        for (int j = 0; j < 8; j++) {
            __nv_bfloat162 p01 = __floats2bfloat162_rn(sc[j][0], sc[j][1]);
            __nv_bfloat162 p23 = __floats2bfloat162_rn(sc[j][2], sc[j][3]);
            ph2[j][0] = *(uint32_t*)&p01;
            ph2[j][1] = *(uint32_t*)&p23;
            float h0 = sc[j][0] - __bfloat162float(p01.x);
            float h1 = sc[j][1] - __bfloat162float(p01.y);
            float h2 = sc[j][2] - __bfloat162float(p23.x);
            float h3 = sc[j][3] - __bfloat162float(p23.y);
            __nv_bfloat162 q01 = __floats2bfloat162_rn(h0, h1);
            __nv_bfloat162 q23 = __floats2bfloat162_rn(h2, h3);
            pl2[j][0] = *(uint32_t*)&q01;
            pl2[j][1] = *(uint32_t*)&q23;
        }

#pragma unroll
        for (int kk = 0; kk < 4; kk++) {
            uint32_t ah[4] = { ph2[2*kk][0], ph2[2*kk][1], ph2[2*kk+1][0], ph2[2*kk+1][1] };
            uint32_t al[4] = { pl2[2*kk][0], pl2[2*kk][1], pl2[2*kk+1][0], pl2[2*kk+1][1] };
#pragma unroll
            for (int j2 = 0; j2 < 8; j2++) {
                uint32_t vhf[4], vlf[4];
                uint32_t voff = (uint32_t)((kk * 16 + vt_r) * V_PITCH + (j2 * 16 + vt_c8) * 2);
                LDSM4T(vhf, vst + voff);
                LDSM4T(vlf, vst + V_HALF + voff);
                MMA16816(O[2*j2],   ah, vhf[0], vhf[1]);
                MMA16816(O[2*j2],   al, vhf[0], vhf[1]);
                MMA16816(O[2*j2],   ah, vlf[0], vlf[1]);
                MMA16816(O[2*j2+1], ah, vhf[2], vhf[3]);
                MMA16816(O[2*j2+1], al, vhf[2], vhf[3]);
                MMA16816(O[2*j2+1], ah, vlf[2], vlf[3]);
            }
        }
        __syncthreads();
    }

    // ---- epilogue: write hi/lo bf16 directly (A operand of G5) ----
    float inv0 = 1.f / l0, inv1 = 1.f / l1;
    size_t ob0 = ((size_t)(b * Ss + qrow0)) * (NHh * VDIM) + h * VDIM;
    size_t ob1 = ((size_t)(b * Ss + qrow1)) * (NHh * VDIM) + h * VDIM;
#pragma unroll
    for (int j = 0; j < 16; j++) {
        int d = j * 8 + t4 * 2;
        __nv_bfloat16 h0, l0v, h1, l1v;
        split_hl(O[j][0] * inv0, h0, l0v);
        split_hl(O[j][1] * inv0, h1, l1v);
        *(__nv_bfloat162*)(oh + ob0 + d) = __nv_bfloat162(h0, h1);
        *(__nv_bfloat162*)(ol + ob0 + d) = __nv_bfloat162(l0v, l1v);
        split_hl(O[j][2] * inv1, h0, l0v);
        split_hl(O[j][3] * inv1, h1, l1v);
        *(__nv_bfloat162*)(oh + ob1 + d) = __nv_bfloat162(h0, h1);
        *(__nv_bfloat162*)(ol + ob1 + d) = __nv_bfloat162(l0v, l1v);
    }
}

// ================= launch =================
extern "C" void kernel_launch(void* const* d_in, const int* in_sizes, int n_in,
                              void* d_out, int out_size) {
    const float* hs     = (const float*)d_in[0];
    const int*   pos    = (const int*)  d_in[1];
    const float* w_q_a  = (const float*)d_in[3];
    const float* q_ln   = (const float*)d_in[4];
    const float* w_q_b  = (const float*)d_in[5];
    const float* w_kv_a = (const float*)d_in[6];
    const float* kv_ln  = (const float*)d_in[7];
    const float* w_kv_b = (const float*)d_in[8];
    const float* w_o    = (const float*)d_in[9];
    float* out = (float*)d_out;

    float *qc, *q, *kvt;
    cudaGetSymbolAddress((void**)&qc,    g_qc);
    cudaGetSymbolAddress((void**)&q,     g_q);
    cudaGetSymbolAddress((void**)&kvt,   g_kvt);

    __nv_bfloat16 *hs_h,*hs_l,*qc_h,*qc_l,*kvc_h,*kvc_l,*at_h,*at_l;
    __nv_bfloat16 *wqa_h,*wqa_l,*wqb_h,*wqb_l,*wkva_h,*wkva_l,*wkvb_h,*wkvb_l,*wo_h,*wo_l;
    __nv_bfloat16 *qfh,*qfl,*kfh,*kfl,*vfh,*vfl;
    cudaGetSymbolAddress((void**)&hs_h,  g_hs_h);  cudaGetSymbolAddress((void**)&hs_l,  g_hs_l);
    cudaGetSymbolAddress((void**)&qc_h,  g_qc_h);  cudaGetSymbolAddress((void**)&qc_l,  g_qc_l);
    cudaGetSymbolAddress((void**)&kvc_h, g_kvc_h); cudaGetSymbolAddress((void**)&kvc_l, g_kvc_l);
    cudaGetSymbolAddress((void**)&at_h,  g_at_h);  cudaGetSymbolAddress((void**)&at_l,  g_at_l);
    cudaGetSymbolAddress((void**)&wqa_h, g_wqa_h); cudaGetSymbolAddress((void**)&wqa_l, g_wqa_l);
    cudaGetSymbolAddress((void**)&wqb_h, g_wqb_h); cudaGetSymbolAddress((void**)&wqb_l, g_wqb_l);
    cudaGetSymbolAddress((void**)&wkva_h,g_wkva_h);cudaGetSymbolAddress((void**)&wkva_l,g_wkva_l);
    cudaGetSymbolAddress((void**)&wkvb_h,g_wkvb_h);cudaGetSymbolAddress((void**)&wkvb_l,g_wkvb_l);
    cudaGetSymbolAddress((void**)&wo_h,  g_wo_h);  cudaGetSymbolAddress((void**)&wo_l,  g_wo_l);
    cudaGetSymbolAddress((void**)&qfh,   g_qfh);   cudaGetSymbolAddress((void**)&qfl,   g_qfl);
    cudaGetSymbolAddress((void**)&kfh,   g_kfh);   cudaGetSymbolAddress((void**)&kfl,   g_kfl);
    cudaGetSymbolAddress((void**)&vfh,   g_vfh);   cudaGetSymbolAddress((void**)&vfl,   g_vfl);

    cudaFuncSetAttribute(mma_gemm_t<0>, cudaFuncAttributeMaxDynamicSharedMemorySize, GEMM_SMEM);
    cudaFuncSetAttribute(mma_gemm_t<1>, cudaFuncAttributeMaxDynamicSharedMemorySize, GEMM_SMEM);
    cudaFuncSetAttribute(flash_mma, cudaFuncAttributeMaxDynamicSharedMemorySize, FLASH_SMEM);

    dim3 tb(32, 8);

    transpose_split<<<dim3(QLORA/32, HID/32), tb>>>(w_q_a, wqa_h, wqa_l, HID, QLORA);
    transpose_split<<<dim3((NHh*QKD)/32, QLORA/32), tb>>>(w_q_b, wqb_h, wqb_l, QLORA, NHh*QKD);
    transpose_split<<<dim3(WKVA_NPAD/32, HID/32), tb>>>(w_kv_a, wkva_h, wkva_l, HID, KVLORA+ROPED);
    transpose_split<<<dim3((NHh*(NOPE+VDIM))/32, KVLORA/32), tb>>>(w_kv_b, wkvb_h, wkvb_l, KVLORA, NHh*(NOPE+VDIM));
    transpose_split<<<dim3(HID/32, (NHh*VDIM)/32), tb>>>(w_o, wo_h, wo_l, NHh*VDIM, HID);
    convert_split<<<(ROWS*(size_t)HID/4 + 255)/256, 256>>>(hs, hs_h, hs_l, (size_t)ROWS*HID);

    // G1: qc = hs @ w_q_a (fp32) ; fused rmsnorm->hi/lo
    mma_gemm_t<0><<<dim3(QLORA/128, ROWS/128), 256, GEMM_SMEM>>>(
        hs_h, hs_l, wqa_h, wqa_l, qc, nullptr, nullptr, nullptr, nullptr, ROWS, QLORA, HID);
    rmsnorm_split<<<ROWS, 256>>>(qc, q_ln, qc_h, qc_l, QLORA);

    // G2: q = qc @ w_q_b (fp32) ; fused rope+scale+prep
    mma_gemm_t<0><<<dim3((NHh*QKD)/128, ROWS/128), 256, GEMM_SMEM>>>(
        qc_h, qc_l, wqb_h, wqb_l, q, nullptr, nullptr, nullptr, nullptr, ROWS, NHh*QKD, QLORA);
    rope_prep_q<<<ROWS, 256>>>(q, pos, qfh, qfl);

    // G3: kvt = hs @ w_kv_a (fp32) ; fused split
    mma_gemm_t<0><<<dim3(WKVA_NPAD/128, ROWS/128), 256, GEMM_SMEM>>>(
        hs_h, hs_l, wkva_h, wkva_l, kvt, nullptr, nullptr, nullptr, nullptr, ROWS, KVLORA+ROPED, HID);
    kv_split2<<<ROWS, 256>>>(kvt, kv_ln, pos, kvc_h, kvc_l, kfh, kfl);

    // G4: kv = kvc @ w_kv_b, scatter epilogue -> K-nope/V final layout hi/lo
    mma_gemm_t<1><<<dim3((NHh*(NOPE+VDIM))/128, ROWS/128), 256, GEMM_SMEM>>>(
        kvc_h, kvc_l, wkvb_h, wkvb_l, nullptr, kfh, kfl, vfh, vfl, ROWS, NHh*(NOPE+VDIM), KVLORA);

    // attention (writes at hi/lo directly)
    flash_mma<<<dim3(Ss/64, NHh, Bb), 128, FLASH_SMEM>>>(qfh, qfl, kfh, kfl, vfh, vfl, at_h, at_l);

    // G5: out = attn @ w_o
    mma_gemm_t<0><<<dim3(HID/128, ROWS/128), 256, GEMM_SMEM>>>(
        at_h, at_l, wo_h, wo_l, out, nullptr, nullptr, nullptr, nullptr, ROWS, HID, HID);
}